// round 9
// baseline (speedup 1.0000x reference)
#include <cuda_runtime.h>
#include <cstdint>
#include <cstddef>

// Problem constants (shapes fixed by the dataset)
#define NNODES 50000
#define NEDGES 800000
#define NCOLS  512
#define NGRAPH 64

// ---------------------------------------------------------------------------
// Scratch (device globals; no allocation allowed)
// ---------------------------------------------------------------------------
__device__ float g_agg[(size_t)NNODES * NCOLS];     // combined (self+agg), tf32-rounded
__device__ float g_z[(size_t)NNODES * NCOLS];
__device__ float g_h1[(size_t)NNODES * NCOLS];
__device__ float g_stats[2 * NCOLS];
__device__ float g_scale[NCOLS];
__device__ float g_shift[NCOLS];
__device__ float g_pooled[(size_t)NGRAPH * NCOLS];
__device__ int   g_src[NEDGES];
__device__ int   g_dst[NEDGES];
__device__ int   g_batch[NNODES];
__device__ int   g_is64;
__device__ int   g_off[NNODES + 1];                 // CSR offsets (by dst)
__device__ int   g_cur[NNODES];                     // deg / cursor
__device__ int   g_bsum[64];                        // scan block sums
__device__ int   g_ssrc[NEDGES];                    // src sorted by dst
__device__ float g_Wt1a[(size_t)NCOLS * 128];       // [N=512][K] tf32 bits
__device__ float g_Wt1b[(size_t)NCOLS * NCOLS];
__device__ float g_Wt2a[(size_t)NCOLS * NCOLS];
__device__ float g_Wt2b[(size_t)NCOLS * NCOLS];

// ---------------------------------------------------------------------------
// PTX helpers
// ---------------------------------------------------------------------------
__device__ __forceinline__ uint32_t smem_u32(const void* p) {
    uint32_t a;
    asm("{ .reg .u64 t; cvta.to.shared.u64 t, %1; cvt.u32.u64 %0, t; }"
        : "=r"(a) : "l"(p));
    return a;
}
__device__ __forceinline__ uint32_t f2tf32(float f) {
    uint32_t u;
    asm("cvt.rna.tf32.f32 %0, %1;" : "=r"(u) : "f"(f));
    return u;
}
__device__ __forceinline__ float4 round_tf32x4(float4 v) {
    return make_float4(__uint_as_float(f2tf32(v.x)), __uint_as_float(f2tf32(v.y)),
                       __uint_as_float(f2tf32(v.z)), __uint_as_float(f2tf32(v.w)));
}
__device__ __forceinline__ void cp16(uint32_t s, const void* g) {
    asm volatile("cp.async.cg.shared.global [%0], [%1], 16;"
                 :: "r"(s), "l"(g) : "memory");
}
__device__ __forceinline__ void red_add_v2(float* addr, float a, float b) {
    asm volatile("red.global.add.v2.f32 [%0], {%1, %2};"
                 :: "l"(addr), "f"(a), "f"(b) : "memory");
}
__device__ __forceinline__ void mma_m16n8k8(float* c, const uint32_t* a,
                                            uint32_t b0, uint32_t b1) {
    asm volatile("mma.sync.aligned.m16n8k8.row.col.f32.tf32.tf32.f32 "
                 "{%0,%1,%2,%3}, {%4,%5,%6,%7}, {%8,%9}, {%0,%1,%2,%3};"
                 : "+f"(c[0]), "+f"(c[1]), "+f"(c[2]), "+f"(c[3])
                 : "r"(a[0]), "r"(a[1]), "r"(a[2]), "r"(a[3]),
                   "r"(b0), "r"(b1));
}

// ---------------------------------------------------------------------------
// Index dtype detection + canonicalization + degree histogram
// ---------------------------------------------------------------------------
__global__ void detect_kernel(const unsigned* __restrict__ ei_words)
{
    unsigned v = ei_words[2 * threadIdx.x + 1];
    unsigned any = __ballot_sync(0xffffffffu, v != 0u);
    __shared__ int s_any;
    if (threadIdx.x == 0) s_any = 0;
    __syncthreads();
    if ((threadIdx.x & 31) == 0 && any) atomicOr(&s_any, 1);
    __syncthreads();
    if (threadIdx.x == 0) g_is64 = (s_any == 0) ? 1 : 0;
}

__global__ void convert_kernel(const void* __restrict__ ei,
                               const void* __restrict__ batch,
                               int E, int N)
{
    int i = blockIdx.x * blockDim.x + threadIdx.x;
    int is64 = g_is64;
    if (i < E) {
        int s, d;
        if (is64) {
            s = (int)((const long long*)ei)[i];
            d = (int)((const long long*)ei)[E + i];
        } else {
            s = ((const int*)ei)[i];
            d = ((const int*)ei)[E + i];
        }
        g_src[i] = s;
        g_dst[i] = d;
        atomicAdd(&g_cur[d], 1);          // fused histogram
    }
    if (i < N) {
        g_batch[i] = is64 ? (int)((const long long*)batch)[i]
                          : ((const int*)batch)[i];
    }
}

// ---------------------------------------------------------------------------
// CSR build: 3-phase parallel exclusive scan, reorder
// ---------------------------------------------------------------------------
__global__ void scan_block(const int* __restrict__ deg, int* __restrict__ off,
                           int* __restrict__ bsum, int n)
{
    __shared__ int wsum[32];
    __shared__ int woff[32];
    __shared__ int total;
    int tid = threadIdx.x, lane = tid & 31, wid = tid >> 5;
    int i = blockIdx.x * 1024 + tid;
    int v = (i < n) ? deg[i] : 0;
    int x = v;
    #pragma unroll
    for (int o = 1; o < 32; o <<= 1) {
        int y = __shfl_up_sync(0xffffffffu, x, o);
        if (lane >= o) x += y;
    }
    if (lane == 31) wsum[wid] = x;
    __syncthreads();
    if (tid < 32) {
        int w = wsum[tid];
        int s = w;
        #pragma unroll
        for (int o = 1; o < 32; o <<= 1) {
            int y = __shfl_up_sync(0xffffffffu, s, o);
            if (tid >= o) s += y;
        }
        woff[tid] = s - w;
        if (tid == 31) total = s;
    }
    __syncthreads();
    if (i < n) off[i] = x + woff[wid] - v;     // block-local exclusive
    if (tid == 0) bsum[blockIdx.x] = total;
}

__global__ void scan_tops(int* __restrict__ bsum, int nb)
{
    __shared__ int sh[64];
    int tid = threadIdx.x;
    int v = (tid < nb) ? bsum[tid] : 0;
    sh[tid] = v;
    __syncthreads();
    #pragma unroll
    for (int o = 1; o < 64; o <<= 1) {
        int t = (tid >= o) ? sh[tid - o] : 0;
        __syncthreads();
        sh[tid] += t;
        __syncthreads();
    }
    if (tid < nb) bsum[tid] = sh[tid] - v;     // exclusive
}

__global__ void scan_add(int* __restrict__ off, int* __restrict__ cur,
                         const int* __restrict__ bsum, int n, int E)
{
    int i = blockIdx.x * 1024 + threadIdx.x;
    if (i < n) {
        int v = off[i] + bsum[blockIdx.x];
        off[i] = v;
        cur[i] = v;                            // fused cursor copy
    }
    if (i == 0) off[n] = E;
}

__global__ void reorder_kernel(int E)
{
    int i = blockIdx.x * blockDim.x + threadIdx.x;
    if (i < E) {
        int d = g_dst[i];
        int p = atomicAdd(&g_cur[d], 1);
        g_ssrc[p] = g_src[i];
    }
}

// ---------------------------------------------------------------------------
// CSR gather: out[v] = tf32(feat[v] + sum_{(u,v)} feat[u]).  One warp per node.
// Unrolled x4 for memory-level parallelism.
// ---------------------------------------------------------------------------
template<int R>
__global__ void gather_csr(const float* __restrict__ feat,
                           float* __restrict__ out, int Nn)
{
    int v = (blockIdx.x * blockDim.x + threadIdx.x) >> 5;
    int lane = threadIdx.x & 31;
    if (v >= Nn) return;
    int e0 = g_off[v], e1 = g_off[v + 1];
    const float4* fp = reinterpret_cast<const float4*>(feat);
    size_t selfb = (size_t)v * (R * 32);
    float4 acc[R];
    #pragma unroll
    for (int r = 0; r < R; r++) acc[r] = fp[selfb + lane + 32 * r];
    int e = e0;
    for (; e + 3 < e1; e += 4) {
        int s0 = g_ssrc[e], s1 = g_ssrc[e + 1], s2 = g_ssrc[e + 2], s3 = g_ssrc[e + 3];
        size_t b0 = (size_t)s0 * (R * 32), b1 = (size_t)s1 * (R * 32);
        size_t b2 = (size_t)s2 * (R * 32), b3 = (size_t)s3 * (R * 32);
        #pragma unroll
        for (int r = 0; r < R; r++) {
            float4 a = fp[b0 + lane + 32 * r];
            float4 b = fp[b1 + lane + 32 * r];
            float4 c = fp[b2 + lane + 32 * r];
            float4 d = fp[b3 + lane + 32 * r];
            acc[r].x += (a.x + b.x) + (c.x + d.x);
            acc[r].y += (a.y + b.y) + (c.y + d.y);
            acc[r].z += (a.z + b.z) + (c.z + d.z);
            acc[r].w += (a.w + b.w) + (c.w + d.w);
        }
    }
    for (; e < e1; e++) {
        size_t bA = (size_t)g_ssrc[e] * (R * 32);
        #pragma unroll
        for (int r = 0; r < R; r++) {
            float4 a = fp[bA + lane + 32 * r];
            acc[r].x += a.x; acc[r].y += a.y; acc[r].z += a.z; acc[r].w += a.w;
        }
    }
    float4* op = reinterpret_cast<float4*>(out);
    #pragma unroll
    for (int r = 0; r < R; r++) op[selfb + lane + 32 * r] = round_tf32x4(acc[r]);
}

// ---------------------------------------------------------------------------
// Merged weight transpose + tf32 pre-round (all 4 matrices, one launch)
// ---------------------------------------------------------------------------
__global__ void transpose_all(const float* __restrict__ W1a, float* __restrict__ T1a,
                              const float* __restrict__ W1b, float* __restrict__ T1b,
                              const float* __restrict__ W2a, float* __restrict__ T2a,
                              const float* __restrict__ W2b, float* __restrict__ T2b)
{
    const float* W; float* T; int K;
    switch (blockIdx.z) {
        case 0:  W = W1a; T = T1a; K = 128;   break;
        case 1:  W = W1b; T = T1b; K = NCOLS; break;
        case 2:  W = W2a; T = T2a; K = NCOLS; break;
        default: W = W2b; T = T2b; K = NCOLS; break;
    }
    int by = blockIdx.y * 32;                  // k block
    if (by >= K) return;
    __shared__ float t[32][33];
    int bx = blockIdx.x * 32;                  // n block
    int x = threadIdx.x, y = threadIdx.y;
    #pragma unroll
    for (int i = 0; i < 32; i += 8)
        t[y + i][x] = W[(size_t)(by + y + i) * NCOLS + bx + x];
    __syncthreads();
    #pragma unroll
    for (int i = 0; i < 32; i += 8)
        T[(size_t)(bx + y + i) * K + by + x] =
            __uint_as_float(f2tf32(t[x][y + i]));
}

// ---------------------------------------------------------------------------
// tf32 mma.sync GEMM, 3-stage cp.async pipeline, 1 sync per K-chunk.
//   D[128,128] per block = Apre[128,K] @ Bt[col0..][K]^T
//   AM==0 : A pre-rounded tf32 in memory -> pure cp.async path
//   AM==1 : A = relu(A0*scale+shift), staged via registers (LDG->preop->STS)
//   EM==0 : store acc; accumulate column sum/sumsq into stats
//   EM==1 : store relu(acc+bias)
//   EM==2 : red-add relu(acc+bias) into pooled[batch[m]]
// Grid: (4 col-blocks, mtiles row-blocks) -> wave covers all cols of few rows
// so A is read from DRAM once (L2 reuse across col-blocks).
// ---------------------------------------------------------------------------
#define BKP 36
#define CH_U32 (128 * BKP)
#define GEMM_SMEM (6 * CH_U32 * 4)      // 110592 B (3-stage, A+B)

template<int AM, int EM>
__global__ void __launch_bounds__(256, 2)
mma_gemm(const int M, const int K,
         const float* __restrict__ A0,
         const float* __restrict__ scale, const float* __restrict__ shift,
         const float* __restrict__ Bt, const float* __restrict__ bias,
         float* __restrict__ C, float* __restrict__ stats,
         float* __restrict__ pooled, const int* __restrict__ batch)
{
    extern __shared__ uint32_t dyn[];
    __shared__ float s_sum[128];
    __shared__ float s_sq[128];
    const uint32_t sbase = smem_u32(dyn);

    const int tid  = threadIdx.x;
    const int lane = tid & 31;
    const int warp = tid >> 5;
    const int grp  = lane >> 2;
    const int tig  = lane & 3;
    const int wm   = (warp >> 1) * 32;
    const int wn   = (warp & 1) * 64;
    const int col0 = blockIdx.x * 128;        // x = column block (4)
    const int row0 = blockIdx.y * 128;        // y = row block (391)

    const int slotRow = tid >> 3;        // 0..31
    const int slotC4  = tid & 7;         // 0..7

    if (EM == 0 && tid < 128) { s_sum[tid] = 0.f; s_sq[tid] = 0.f; }

    float acc[2][8][4];
    #pragma unroll
    for (int mt = 0; mt < 2; mt++)
        #pragma unroll
        for (int nt = 0; nt < 8; nt++)
            #pragma unroll
            for (int q = 0; q < 4; q++) acc[mt][nt][q] = 0.f;

    const int NC = K >> 5;               // 4 or 16 (always >= 2)
    float4 aR[4];                        // AM==1 register staging

    auto cpB = [&](int ci, int buf) {
        const int k0 = ci << 5;
        #pragma unroll
        for (int r = 0; r < 4; r++) {
            int row = slotRow + r * 32;
            cp16(sbase + (3 + buf) * (CH_U32 * 4) +
                     (uint32_t)(row * BKP + slotC4 * 4) * 4,
                 Bt + (size_t)(col0 + row) * K + k0 + slotC4 * 4);
        }
    };
    auto cpA = [&](int ci, int buf) {    // AM==0 only (pre-rounded input)
        const int k0 = ci << 5;
        #pragma unroll
        for (int r = 0; r < 4; r++) {
            int row = slotRow + r * 32;
            int gr = row0 + row;
            if (gr < M) {
                cp16(sbase + buf * (CH_U32 * 4) +
                         (uint32_t)(row * BKP + slotC4 * 4) * 4,
                     A0 + (size_t)gr * K + k0 + slotC4 * 4);
            } else {
                *reinterpret_cast<uint4*>(&dyn[buf * CH_U32 + row * BKP + slotC4 * 4]) =
                    make_uint4(0u, 0u, 0u, 0u);
            }
        }
    };
    auto ldA = [&](int ci) {             // AM==1: LDG chunk into registers
        const int k0 = ci << 5;
        #pragma unroll
        for (int r = 0; r < 4; r++) {
            int gr = row0 + slotRow + r * 32;
            aR[r] = (gr < M)
                ? *reinterpret_cast<const float4*>(A0 + (size_t)gr * K + k0 + slotC4 * 4)
                : make_float4(0.f, 0.f, 0.f, 0.f);
        }
    };
    auto stA = [&](int ci, int buf) {    // AM==1: preop + cvt + STS
        const int k0 = ci << 5;
        float4 sc = *reinterpret_cast<const float4*>(scale + k0 + slotC4 * 4);
        float4 sh = *reinterpret_cast<const float4*>(shift + k0 + slotC4 * 4);
        #pragma unroll
        for (int r = 0; r < 4; r++) {
            int row = slotRow + r * 32;
            float4 v = aR[r];
            v.x = fmaxf(fmaf(v.x, sc.x, sh.x), 0.f);
            v.y = fmaxf(fmaf(v.y, sc.y, sh.y), 0.f);
            v.z = fmaxf(fmaf(v.z, sc.z, sh.z), 0.f);
            v.w = fmaxf(fmaf(v.w, sc.w, sh.w), 0.f);
            *reinterpret_cast<uint4*>(&dyn[buf * CH_U32 + row * BKP + slotC4 * 4]) =
                make_uint4(f2tf32(v.x), f2tf32(v.y), f2tf32(v.z), f2tf32(v.w));
        }
    };

    // ---- prologue: chunks 0 and 1 (2 groups in flight) ----
    if (AM == 0) {
        cpA(0, 0); cpB(0, 0);
        asm volatile("cp.async.commit_group;" ::: "memory");
        cpA(1, 1); cpB(1, 1);
        asm volatile("cp.async.commit_group;" ::: "memory");
    } else {
        ldA(0); stA(0, 0);
        ldA(1); stA(1, 1);
        cpB(0, 0);
        asm volatile("cp.async.commit_group;" ::: "memory");
        cpB(1, 1);
        asm volatile("cp.async.commit_group;" ::: "memory");
        if (NC > 2) ldA(2);
    }

    // ---- mainloop: one __syncthreads per chunk ----
    for (int i = 0; i < NC; i++) {
        const int buf = i % 3;
        if (i + 2 < NC) {
            asm volatile("cp.async.wait_group 1;" ::: "memory");
        } else {
            asm volatile("cp.async.wait_group 0;" ::: "memory");
        }
        __syncthreads();
        if (i + 2 < NC) {
            const int nb = (i + 2) % 3;
            if (AM == 0) {
                cpA(i + 2, nb); cpB(i + 2, nb);
                asm volatile("cp.async.commit_group;" ::: "memory");
            } else {
                stA(i + 2, nb);
                cpB(i + 2, nb);
                asm volatile("cp.async.commit_group;" ::: "memory");
                if (i + 3 < NC) ldA(i + 3);
            }
        }

        const uint32_t* As = &dyn[buf * CH_U32];
        const uint32_t* Bs = &dyn[(3 + buf) * CH_U32];
        #pragma unroll
        for (int ks = 0; ks < 4; ks++) {
            const int kk = ks * 8;
            uint32_t a[2][4];
            #pragma unroll
            for (int mt = 0; mt < 2; mt++) {
                int rbase = (wm + mt * 16 + grp) * BKP + kk;
                a[mt][0] = As[rbase + tig];
                a[mt][1] = As[rbase + 8 * BKP + tig];
                a[mt][2] = As[rbase + tig + 4];
                a[mt][3] = As[rbase + 8 * BKP + tig + 4];
            }
            #pragma unroll
            for (int nt = 0; nt < 8; nt++) {
                int nbase = (wn + nt * 8 + grp) * BKP + kk;
                uint32_t b0 = Bs[nbase + tig];
                uint32_t b1 = Bs[nbase + tig + 4];
                mma_m16n8k8(acc[0][nt], a[0], b0, b1);
                mma_m16n8k8(acc[1][nt], a[1], b0, b1);
            }
        }
        __syncthreads();
    }

    // ---- epilogue ----
    #pragma unroll
    for (int nt = 0; nt < 8; nt++) {
        float cs0 = 0.f, cq0 = 0.f, cs1 = 0.f, cq1 = 0.f;
        #pragma unroll
        for (int mt = 0; mt < 2; mt++) {
            #pragma unroll
            for (int half = 0; half < 2; half++) {
                int gm = row0 + wm + mt * 16 + grp + half * 8;
                if (gm >= M) continue;
                int col = col0 + wn + nt * 8 + 2 * tig;
                float v0 = acc[mt][nt][2 * half];
                float v1 = acc[mt][nt][2 * half + 1];
                if (EM == 0) {
                    cs0 += v0; cq0 += v0 * v0;
                    cs1 += v1; cq1 += v1 * v1;
                    *reinterpret_cast<float2*>(C + (size_t)gm * NCOLS + col) =
                        make_float2(v0, v1);
                } else {
                    v0 = fmaxf(v0 + __ldg(bias + col),     0.f);
                    v1 = fmaxf(v1 + __ldg(bias + col + 1), 0.f);
                    if (EM == 2) {
                        red_add_v2(pooled + (size_t)batch[gm] * NCOLS + col, v0, v1);
                    } else {
                        *reinterpret_cast<float2*>(C + (size_t)gm * NCOLS + col) =
                            make_float2(v0, v1);
                    }
                }
            }
        }
        if (EM == 0) {
            #pragma unroll
            for (int o = 4; o < 32; o <<= 1) {
                cs0 += __shfl_xor_sync(0xffffffffu, cs0, o);
                cq0 += __shfl_xor_sync(0xffffffffu, cq0, o);
                cs1 += __shfl_xor_sync(0xffffffffu, cs1, o);
                cq1 += __shfl_xor_sync(0xffffffffu, cq1, o);
            }
            if (grp == 0) {
                int lc = wn + nt * 8 + 2 * tig;
                atomicAdd(&s_sum[lc],     cs0);
                atomicAdd(&s_sq[lc],      cq0);
                atomicAdd(&s_sum[lc + 1], cs1);
                atomicAdd(&s_sq[lc + 1],  cq1);
            }
        }
    }
    if (EM == 0) {
        __syncthreads();
        if (tid < 128) {
            atomicAdd(&stats[col0 + tid],         s_sum[tid]);
            atomicAdd(&stats[NCOLS + col0 + tid], s_sq[tid]);
        }
    }
}

// ---------------------------------------------------------------------------
// BN stats -> fused scale/shift
// ---------------------------------------------------------------------------
__global__ void bn_finalize(const float* __restrict__ stats,
                            const float* __restrict__ gamma,
                            const float* __restrict__ beta,
                            float* __restrict__ scale,
                            float* __restrict__ shift,
                            float invN)
{
    int c = threadIdx.x;
    float mean = stats[c] * invN;
    float var  = stats[NCOLS + c] * invN - mean * mean;
    float s = gamma[c] * rsqrtf(var + 1e-5f);
    scale[c] = s;
    shift[c] = beta[c] - mean * s;
}

// ---------------------------------------------------------------------------
// Head MLP: out = relu(pooled @ Wl1 + bl1) @ Wl2 + bl2   (64 x 10)
// ---------------------------------------------------------------------------
__global__ void head_kernel(const float* __restrict__ pooled,
                            const float* __restrict__ Wl1,
                            const float* __restrict__ bl1,
                            const float* __restrict__ Wl2,
                            const float* __restrict__ bl2,
                            float* __restrict__ out, int OUTC)
{
    __shared__ float sp[NCOLS];
    __shared__ float sh[NCOLS];
    int g = blockIdx.x, t = threadIdx.x;
    sp[t] = pooled[(size_t)g * NCOLS + t];
    __syncthreads();
    float a = bl1[t];
    for (int k = 0; k < NCOLS; k++)
        a = fmaf(sp[k], Wl1[(size_t)k * NCOLS + t], a);
    sh[t] = fmaxf(a, 0.f);
    __syncthreads();
    if (t < 32 * OUTC) {
        int w = t >> 5, l = t & 31;
        float s = 0.f;
        for (int k = l; k < NCOLS; k += 32)
            s = fmaf(sh[k], Wl2[(size_t)k * OUTC + w], s);
        #pragma unroll
        for (int o = 16; o; o >>= 1)
            s += __shfl_down_sync(0xffffffffu, s, o);
        if (l == 0) out[(size_t)g * OUTC + w] = s + bl2[w];
    }
}

// ---------------------------------------------------------------------------
// Launch
// ---------------------------------------------------------------------------
extern "C" void kernel_launch(void* const* d_in, const int* in_sizes, int n_in,
                              void* d_out, int out_size)
{
    const float* x     = (const float*)d_in[0];
    const void*  ei    = d_in[1];
    const void*  batch = d_in[2];
    const float* W1a = (const float*)d_in[3];
    const float* g1  = (const float*)d_in[5];
    const float* be1 = (const float*)d_in[6];
    const float* W1b = (const float*)d_in[7];
    const float* b1b = (const float*)d_in[8];
    const float* W2a = (const float*)d_in[9];
    const float* g2  = (const float*)d_in[11];
    const float* be2 = (const float*)d_in[12];
    const float* W2b = (const float*)d_in[13];
    const float* b2b = (const float*)d_in[14];
    const float* Wl1 = (const float*)d_in[15];
    const float* bl1 = (const float*)d_in[16];
    const float* Wl2 = (const float*)d_in[17];
    const float* bl2 = (const float*)d_in[18];
    float* out = (float*)d_out;

    const int IN   = 128;
    const int N    = in_sizes[0] / IN;        // 50000
    const int E    = in_sizes[1] / 2;         // 800000
    const int OUTC = in_sizes[18];            // 10
    const int G    = out_size / OUTC;         // 64

    float *comb, *z, *h1, *stats, *scale, *shift, *pooled;
    float *Wt1a, *Wt1b, *Wt2a, *Wt2b;
    int *batchI, *offI, *curI, *bsumI;
    cudaGetSymbolAddress((void**)&comb,   g_agg);
    cudaGetSymbolAddress((void**)&z,      g_z);
    cudaGetSymbolAddress((void**)&h1,     g_h1);
    cudaGetSymbolAddress((void**)&stats,  g_stats);
    cudaGetSymbolAddress((void**)&scale,  g_scale);
    cudaGetSymbolAddress((void**)&shift,  g_shift);
    cudaGetSymbolAddress((void**)&pooled, g_pooled);
    cudaGetSymbolAddress((void**)&batchI, g_batch);
    cudaGetSymbolAddress((void**)&offI,   g_off);
    cudaGetSymbolAddress((void**)&curI,   g_cur);
    cudaGetSymbolAddress((void**)&bsumI,  g_bsum);
    cudaGetSymbolAddress((void**)&Wt1a,   g_Wt1a);
    cudaGetSymbolAddress((void**)&Wt1b,   g_Wt1b);
    cudaGetSymbolAddress((void**)&Wt2a,   g_Wt2a);
    cudaGetSymbolAddress((void**)&Wt2b,   g_Wt2b);

    cudaFuncSetAttribute(mma_gemm<0, 0>, cudaFuncAttributeMaxDynamicSharedMemorySize, GEMM_SMEM);
    cudaFuncSetAttribute(mma_gemm<1, 1>, cudaFuncAttributeMaxDynamicSharedMemorySize, GEMM_SMEM);
    cudaFuncSetAttribute(mma_gemm<1, 2>, cudaFuncAttributeMaxDynamicSharedMemorySize, GEMM_SMEM);

    // ---- canonicalize indices (+hist); build CSR; transpose weights ----
    detect_kernel<<<1, 128>>>((const unsigned*)ei);
    cudaMemsetAsync(curI, 0, (size_t)N * sizeof(int));
    convert_kernel<<<(E + 255) / 256, 256>>>(ei, batch, E, N);
    const int nb = (N + 1023) / 1024;         // 49
    scan_block<<<nb, 1024>>>(curI, offI, bsumI, N);
    scan_tops<<<1, 64>>>(bsumI, nb);
    scan_add<<<nb, 1024>>>(offI, curI, bsumI, N, E);
    reorder_kernel<<<(E + 255) / 256, 256>>>(E);
    transpose_all<<<dim3(16, 16, 4), dim3(32, 8)>>>(W1a, Wt1a, W1b, Wt1b,
                                                    W2a, Wt2a, W2b, Wt2b);

    const int mtiles = (N + 127) / 128;
    const dim3 ggrid(4, mtiles);              // col-block fastest -> L2 A reuse
    const int gatherBlocks = (N * 32 + 255) / 256;

    // ---------------- Layer 1 ----------------
    cudaMemsetAsync(stats, 0, 2 * NCOLS * sizeof(float));
    gather_csr<1><<<gatherBlocks, 256>>>(x, comb, N);
    mma_gemm<0, 0><<<ggrid, 256, GEMM_SMEM>>>(N, IN, comb, nullptr, nullptr,
                                              Wt1a, nullptr, z, stats, nullptr, nullptr);
    bn_finalize<<<1, NCOLS>>>(stats, g1, be1, scale, shift, 1.0f / N);
    mma_gemm<1, 1><<<ggrid, 256, GEMM_SMEM>>>(N, NCOLS, z, scale, shift,
                                              Wt1b, b1b, h1, nullptr, nullptr, nullptr);

    // ---------------- Layer 2 ----------------
    cudaMemsetAsync(stats, 0, 2 * NCOLS * sizeof(float));
    gather_csr<4><<<gatherBlocks, 256>>>(h1, comb, N);
    mma_gemm<0, 0><<<ggrid, 256, GEMM_SMEM>>>(N, NCOLS, comb, nullptr, nullptr,
                                              Wt2a, nullptr, z, stats, nullptr, nullptr);
    bn_finalize<<<1, NCOLS>>>(stats, g2, be2, scale, shift, 1.0f / N);
    cudaMemsetAsync(pooled, 0, (size_t)G * NCOLS * sizeof(float));
    mma_gemm<1, 2><<<ggrid, 256, GEMM_SMEM>>>(N, NCOLS, z, scale, shift,
                                              Wt2b, b2b, nullptr, nullptr, pooled, batchI);

    // ---------------- Head ----------------
    head_kernel<<<G, NCOLS>>>(pooled, Wl1, bl1, Wl2, bl2, out, OUTC);
}

// round 13
// speedup vs baseline: 1.1044x; 1.1044x over previous
#include <cuda_runtime.h>
#include <cuda_bf16.h>
#include <cstdint>
#include <cstddef>

// Problem constants (shapes fixed by the dataset)
#define NNODES 50000
#define NEDGES 800000
#define NCOLS  512
#define NGRAPH 64

// ---------------------------------------------------------------------------
// Scratch (device globals; zero-initialized at module load; no allocation)
// Self-cleaning scheme: g_cur / g_stats / g_pooled are re-zeroed by late
// kernels of each run so every graph replay starts from the same state.
// ---------------------------------------------------------------------------
__device__ float        g_agg[(size_t)NNODES * NCOLS];   // comb (self+agg), tf32
__device__ float        g_z[(size_t)NNODES * NCOLS];     // pre-BN z
__device__ __nv_bfloat16 g_h1b[(size_t)NNODES * NCOLS];  // layer-1 output (bf16)
__device__ float        g_stats[2 * NCOLS];              // col sum / sumsq
__device__ float        g_pooled[(size_t)NGRAPH * NCOLS];
__device__ int          g_src[NEDGES];
__device__ int          g_dst[NEDGES];
__device__ int          g_batch[NNODES];
__device__ int          g_off[NNODES + 1];
__device__ int          g_cur[NNODES];
__device__ int          g_bsum[64];
__device__ int          g_ssrc[NEDGES];
__device__ float        g_Wt1a[(size_t)NCOLS * 128];     // [N][K] tf32 bits
__device__ float        g_Wt1b[(size_t)NCOLS * NCOLS];
__device__ float        g_Wt2a[(size_t)NCOLS * NCOLS];
__device__ float        g_Wt2b[(size_t)NCOLS * NCOLS];

// ---------------------------------------------------------------------------
// PTX helpers
// ---------------------------------------------------------------------------
__device__ __forceinline__ uint32_t smem_u32(const void* p) {
    uint32_t a;
    asm("{ .reg .u64 t; cvta.to.shared.u64 t, %1; cvt.u32.u64 %0, t; }"
        : "=r"(a) : "l"(p));
    return a;
}
__device__ __forceinline__ uint32_t f2tf32(float f) {
    uint32_t u;
    asm("cvt.rna.tf32.f32 %0, %1;" : "=r"(u) : "f"(f));
    return u;
}
__device__ __forceinline__ float4 round_tf32x4(float4 v) {
    return make_float4(__uint_as_float(f2tf32(v.x)), __uint_as_float(f2tf32(v.y)),
                       __uint_as_float(f2tf32(v.z)), __uint_as_float(f2tf32(v.w)));
}
__device__ __forceinline__ void cp16(uint32_t s, const void* g) {
    asm volatile("cp.async.cg.shared.global [%0], [%1], 16;"
                 :: "r"(s), "l"(g) : "memory");
}
__device__ __forceinline__ void red_add_v2(float* addr, float a, float b) {
    asm volatile("red.global.add.v2.f32 [%0], {%1, %2};"
                 :: "l"(addr), "f"(a), "f"(b) : "memory");
}
__device__ __forceinline__ void mma_m16n8k8(float* c, const uint32_t* a,
                                            uint32_t b0, uint32_t b1) {
    asm volatile("mma.sync.aligned.m16n8k8.row.col.f32.tf32.tf32.f32 "
                 "{%0,%1,%2,%3}, {%4,%5,%6,%7}, {%8,%9}, {%0,%1,%2,%3};"
                 : "+f"(c[0]), "+f"(c[1]), "+f"(c[2]), "+f"(c[3])
                 : "r"(a[0]), "r"(a[1]), "r"(a[2]), "r"(a[3]),
                   "r"(b0), "r"(b1));
}

// ---------------------------------------------------------------------------
// prep: (y==0)  index dtype detect + canonicalize + degree histogram
//       (y>=1)  weight transpose + tf32 pre-round, one matrix per y
// g_cur must be zero on entry: zero-init at load; head_kernel re-zeroes.
// ---------------------------------------------------------------------------
__global__ void prep_kernel(const void* __restrict__ ei,
                            const void* __restrict__ batch, int E, int N,
                            const float* __restrict__ W1a,
                            const float* __restrict__ W1b,
                            const float* __restrict__ W2a,
                            const float* __restrict__ W2b)
{
    if (blockIdx.y == 0) {
        int i = blockIdx.x * 256 + threadIdx.x;
        unsigned w = 0;
        if (i < E) w = ((const unsigned*)ei)[2 * i + 1];
        int is64 = (__syncthreads_or(w != 0u) == 0);
        if (i < E) {
            int s, d;
            if (is64) {
                s = (int)((const long long*)ei)[i];
                d = (int)((const long long*)ei)[E + i];
            } else {
                s = ((const int*)ei)[i];
                d = ((const int*)ei)[E + i];
            }
            g_src[i] = s;
            g_dst[i] = d;
            atomicAdd(&g_cur[d], 1);
        }
        if (i < N) {
            g_batch[i] = is64 ? (int)((const long long*)batch)[i]
                              : ((const int*)batch)[i];
        }
    } else {
        const float* W; float* T; int K;
        switch (blockIdx.y) {
            case 1:  W = W1a; T = g_Wt1a; K = 128;   break;
            case 2:  W = W1b; T = g_Wt1b; K = NCOLS; break;
            case 3:  W = W2a; T = g_Wt2a; K = NCOLS; break;
            default: W = W2b; T = g_Wt2b; K = NCOLS; break;
        }
        if ((int)blockIdx.x >= 16 * (K / 32)) return;
        __shared__ float t[32][33];
        int bx = (blockIdx.x & 15) * 32;      // n block
        int by = (blockIdx.x >> 4) * 32;      // k block
        int x = threadIdx.x & 31, y = threadIdx.x >> 5;   // y: 0..7
        #pragma unroll
        for (int i = 0; i < 32; i += 8)
            t[y + i][x] = W[(size_t)(by + y + i) * NCOLS + bx + x];
        __syncthreads();
        #pragma unroll
        for (int i = 0; i < 32; i += 8)
            T[(size_t)(bx + y + i) * K + by + x] =
                __uint_as_float(f2tf32(t[x][y + i]));
    }
}

// ---------------------------------------------------------------------------
// CSR build: block scan, then per-block prefix-of-blocksums + add + cursor
// ---------------------------------------------------------------------------
__global__ void scan_block(const int* __restrict__ deg, int* __restrict__ off,
                           int* __restrict__ bsum, int n)
{
    __shared__ int wsum[32];
    __shared__ int woff[32];
    __shared__ int total;
    int tid = threadIdx.x, lane = tid & 31, wid = tid >> 5;
    int i = blockIdx.x * 1024 + tid;
    int v = (i < n) ? deg[i] : 0;
    int x = v;
    #pragma unroll
    for (int o = 1; o < 32; o <<= 1) {
        int y = __shfl_up_sync(0xffffffffu, x, o);
        if (lane >= o) x += y;
    }
    if (lane == 31) wsum[wid] = x;
    __syncthreads();
    if (tid < 32) {
        int w = wsum[tid];
        int s = w;
        #pragma unroll
        for (int o = 1; o < 32; o <<= 1) {
            int y = __shfl_up_sync(0xffffffffu, s, o);
            if (tid >= o) s += y;
        }
        woff[tid] = s - w;
        if (tid == 31) total = s;
    }
    __syncthreads();
    if (i < n) off[i] = x + woff[wid] - v;
    if (tid == 0) bsum[blockIdx.x] = total;
}

__global__ void scan_add2(int* __restrict__ off, int* __restrict__ cur,
                          const int* __restrict__ bsum, int n, int E)
{
    int b = blockIdx.x;
    int pre = 0;
    for (int j = 0; j < b; j++) pre += bsum[j];
    int i = b * 1024 + threadIdx.x;
    if (i < n) {
        int v = off[i] + pre;
        off[i] = v;
        cur[i] = v;
    }
    if (b == 0 && threadIdx.x == 0) off[n] = E;
}

__global__ void reorder_kernel(int E)
{
    int i = blockIdx.x * blockDim.x + threadIdx.x;
    if (i < E) {
        int d = g_dst[i];
        int p = atomicAdd(&g_cur[d], 1);
        g_ssrc[p] = g_src[i];
    }
}

// ---------------------------------------------------------------------------
// CSR gather (fp32): out[v] = tf32(feat[v] + sum feat[u]).  Warp per node.
// ---------------------------------------------------------------------------
template<int R>
__global__ void gather_csr(const float* __restrict__ feat,
                           float* __restrict__ out, int Nn)
{
    int v = (blockIdx.x * blockDim.x + threadIdx.x) >> 5;
    int lane = threadIdx.x & 31;
    if (v >= Nn) return;
    int e0 = g_off[v], e1 = g_off[v + 1];
    const float4* fp = reinterpret_cast<const float4*>(feat);
    size_t selfb = (size_t)v * (R * 32);
    float4 acc[R];
    #pragma unroll
    for (int r = 0; r < R; r++) acc[r] = fp[selfb + lane + 32 * r];
    int e = e0;
    for (; e + 3 < e1; e += 4) {
        int s0 = g_ssrc[e], s1 = g_ssrc[e + 1], s2 = g_ssrc[e + 2], s3 = g_ssrc[e + 3];
        size_t b0 = (size_t)s0 * (R * 32), b1 = (size_t)s1 * (R * 32);
        size_t b2 = (size_t)s2 * (R * 32), b3 = (size_t)s3 * (R * 32);
        #pragma unroll
        for (int r = 0; r < R; r++) {
            float4 a = fp[b0 + lane + 32 * r];
            float4 b = fp[b1 + lane + 32 * r];
            float4 c = fp[b2 + lane + 32 * r];
            float4 d = fp[b3 + lane + 32 * r];
            acc[r].x += (a.x + b.x) + (c.x + d.x);
            acc[r].y += (a.y + b.y) + (c.y + d.y);
            acc[r].z += (a.z + b.z) + (c.z + d.z);
            acc[r].w += (a.w + b.w) + (c.w + d.w);
        }
    }
    for (; e < e1; e++) {
        size_t bA = (size_t)g_ssrc[e] * (R * 32);
        #pragma unroll
        for (int r = 0; r < R; r++) {
            float4 a = fp[bA + lane + 32 * r];
            acc[r].x += a.x; acc[r].y += a.y; acc[r].z += a.z; acc[r].w += a.w;
        }
    }
    float4* op = reinterpret_cast<float4*>(out);
    #pragma unroll
    for (int r = 0; r < R; r++) op[selfb + lane + 32 * r] = round_tf32x4(acc[r]);
}

// ---------------------------------------------------------------------------
// CSR gather (bf16 input): layer 2.  Also zeroes g_stats (block 0) so the
// following GEMM can accumulate.  Warp per node, 2 x uint4 (=16 bf16) / lane.
// ---------------------------------------------------------------------------
__device__ __forceinline__ void acc8_bf16(float* a, uint4 raw) {
    float2 p;
    p = __bfloat1622float2(*reinterpret_cast<__nv_bfloat162*>(&raw.x));
    a[0] += p.x; a[1] += p.y;
    p = __bfloat1622float2(*reinterpret_cast<__nv_bfloat162*>(&raw.y));
    a[2] += p.x; a[3] += p.y;
    p = __bfloat1622float2(*reinterpret_cast<__nv_bfloat162*>(&raw.z));
    a[4] += p.x; a[5] += p.y;
    p = __bfloat1622float2(*reinterpret_cast<__nv_bfloat162*>(&raw.w));
    a[6] += p.x; a[7] += p.y;
}

__global__ void gather_bf16(const __nv_bfloat16* __restrict__ feat,
                            float* __restrict__ out, int Nn)
{
    if (blockIdx.x == 0) {
        for (int c = threadIdx.x; c < 2 * NCOLS; c += 256) g_stats[c] = 0.f;
    }
    int v = (blockIdx.x * blockDim.x + threadIdx.x) >> 5;
    int lane = threadIdx.x & 31;
    if (v >= Nn) return;
    int e0 = g_off[v], e1 = g_off[v + 1];
    const uint4* fp = reinterpret_cast<const uint4*>(feat);   // 64 uint4/row
    size_t selfb = (size_t)v * 64;
    float acc[16];
    #pragma unroll
    for (int q = 0; q < 16; q++) acc[q] = 0.f;
    #pragma unroll
    for (int r = 0; r < 2; r++) acc8_bf16(&acc[8 * r], fp[selfb + lane + 32 * r]);
    int e = e0;
    for (; e + 3 < e1; e += 4) {
        size_t b0 = (size_t)g_ssrc[e]     * 64;
        size_t b1 = (size_t)g_ssrc[e + 1] * 64;
        size_t b2 = (size_t)g_ssrc[e + 2] * 64;
        size_t b3 = (size_t)g_ssrc[e + 3] * 64;
        #pragma unroll
        for (int r = 0; r < 2; r++) {
            uint4 ra = fp[b0 + lane + 32 * r];
            uint4 rb = fp[b1 + lane + 32 * r];
            uint4 rc = fp[b2 + lane + 32 * r];
            uint4 rd = fp[b3 + lane + 32 * r];
            acc8_bf16(&acc[8 * r], ra);
            acc8_bf16(&acc[8 * r], rb);
            acc8_bf16(&acc[8 * r], rc);
            acc8_bf16(&acc[8 * r], rd);
        }
    }
    for (; e < e1; e++) {
        size_t bA = (size_t)g_ssrc[e] * 64;
        #pragma unroll
        for (int r = 0; r < 2; r++) acc8_bf16(&acc[8 * r], fp[bA + lane + 32 * r]);
    }
    float4* op = reinterpret_cast<float4*>(out);
    #pragma unroll
    for (int r = 0; r < 2; r++) {
        int q = lane + 32 * r;
        float4 lo = round_tf32x4(make_float4(acc[8*r+0], acc[8*r+1], acc[8*r+2], acc[8*r+3]));
        float4 hi = round_tf32x4(make_float4(acc[8*r+4], acc[8*r+5], acc[8*r+6], acc[8*r+7]));
        op[(size_t)v * 128 + 2 * q]     = lo;
        op[(size_t)v * 128 + 2 * q + 1] = hi;
    }
}

// ---------------------------------------------------------------------------
// tf32 mma.sync GEMM, 2-stage cp.async, 1 sync per K-chunk.
//   AM==0 : A pre-rounded tf32 in memory (cp.async path)
//   AM==1 : A = relu(A0*scale+shift); scale/shift computed in-kernel from
//           stats/gamma/beta (BatchNorm folded); A staged via registers.
//   EM==0 : store z (fp32) + accumulate column stats
//   EM==1 : store relu(acc+bias) as bf16 (h1)
//   EM==2 : red-add relu(acc+bias) into pooled[batch[m]]
// ---------------------------------------------------------------------------
#define BKP 36
#define CH_U32 (128 * BKP)
#define GEMM_SMEM (4 * CH_U32 * 4)      // 73728 B (2-stage)

template<int AM, int EM>
__global__ void __launch_bounds__(256, 2)
mma_gemm(const int M, const int K,
         const float* __restrict__ A0,
         const float* __restrict__ gamma, const float* __restrict__ beta,
         const float invN,
         const float* __restrict__ Bt, const float* __restrict__ bias,
         float* __restrict__ C, float* __restrict__ stats,
         float* __restrict__ pooled, const int* __restrict__ batch)
{
    extern __shared__ uint32_t dyn[];
    __shared__ float s_sum[128];
    __shared__ float s_sq[128];
    __shared__ float s_scale[NCOLS];
    __shared__ float s_shift[NCOLS];
    const uint32_t sbase = smem_u32(dyn);

    const int tid  = threadIdx.x;
    const int lane = tid & 31;
    const int warp = tid >> 5;
    const int grp  = lane >> 2;
    const int tig  = lane & 3;
    const int wm   = (warp >> 1) * 32;
    const int wn   = (warp & 1) * 64;
    const int col0 = blockIdx.x * 128;
    const int row0 = blockIdx.y * 128;

    const int slotRow = tid >> 3;
    const int slotC4  = tid & 7;

    if (EM == 0 && tid < 128) { s_sum[tid] = 0.f; s_sq[tid] = 0.f; }
    if (AM == 1) {
        for (int c = tid; c < NCOLS; c += 256) {
            float mean = stats[c] * invN;
            float var  = stats[NCOLS + c] * invN - mean * mean;
            float s = gamma[c] * rsqrtf(var + 1e-5f);
            s_scale[c] = s;
            s_shift[c] = beta[c] - mean * s;
        }
    }

    float acc[2][8][4];
    #pragma unroll
    for (int mt = 0; mt < 2; mt++)
        #pragma unroll
        for (int nt = 0; nt < 8; nt++)
            #pragma unroll
            for (int q = 0; q < 4; q++) acc[mt][nt][q] = 0.f;

    const int NC = K >> 5;
    float4 aR[4];

    auto cpB = [&](int ci, int buf) {
        const int k0 = ci << 5;
        #pragma unroll
        for (int r = 0; r < 4; r++) {
            int row = slotRow + r * 32;
            cp16(sbase + (2 + buf) * (CH_U32 * 4) +
                     (uint32_t)(row * BKP + slotC4 * 4) * 4,
                 Bt + (size_t)(col0 + row) * K + k0 + slotC4 * 4);
        }
    };
    auto cpA = [&](int ci, int buf) {
        const int k0 = ci << 5;
        #pragma unroll
        for (int r = 0; r < 4; r++) {
            int row = slotRow + r * 32;
            int gr = row0 + row;
            if (gr < M) {
                cp16(sbase + buf * (CH_U32 * 4) +
                         (uint32_t)(row * BKP + slotC4 * 4) * 4,
                     A0 + (size_t)gr * K + k0 + slotC4 * 4);
            } else {
                *reinterpret_cast<uint4*>(&dyn[buf * CH_U32 + row * BKP + slotC4 * 4]) =
                    make_uint4(0u, 0u, 0u, 0u);
            }
        }
    };
    auto ldA = [&](int ci) {
        const int k0 = ci << 5;
        #pragma unroll
        for (int r = 0; r < 4; r++) {
            int gr = row0 + slotRow + r * 32;
            aR[r] = (gr < M)
                ? *reinterpret_cast<const float4*>(A0 + (size_t)gr * K + k0 + slotC4 * 4)
                : make_float4(0.f, 0.f, 0.f, 0.f);
        }
    };
    auto stA = [&](int ci, int buf) {
        const int k0 = ci << 5;
        float4 sc = *reinterpret_cast<const float4*>(&s_scale[k0 + slotC4 * 4]);
        float4 sh = *reinterpret_cast<const float4*>(&s_shift[k0 + slotC4 * 4]);
        #pragma unroll
        for (int r = 0; r < 4; r++) {
            int row = slotRow + r * 32;
            float4 v = aR[r];
            v.x = fmaxf(fmaf(v.x, sc.x, sh.x), 0.f);
            v.y = fmaxf(fmaf(v.y, sc.y, sh.y), 0.f);
            v.z = fmaxf(fmaf(v.z, sc.z, sh.z), 0.f);
            v.w = fmaxf(fmaf(v.w, sc.w, sh.w), 0.f);
            *reinterpret_cast<uint4*>(&dyn[buf * CH_U32 + row * BKP + slotC4 * 4]) =
                make_uint4(f2tf32(v.x), f2tf32(v.y), f2tf32(v.z), f2tf32(v.w));
        }
    };

    // ---- prologue: chunk 0 ----
    if (AM == 0) cpA(0, 0);
    cpB(0, 0);
    asm volatile("cp.async.commit_group;" ::: "memory");
    if (AM == 1) {
        __syncthreads();          // s_scale/s_shift ready
        ldA(0);
        stA(0, 0);
        if (NC > 1) ldA(1);
    }

    // ---- mainloop ----
    for (int i = 0; i < NC; i++) {
        const int buf = i & 1;
        const int nb  = buf ^ 1;
        asm volatile("cp.async.wait_group 0;" ::: "memory");
        __syncthreads();
        if (i + 1 < NC) {
            if (AM == 0) cpA(i + 1, nb);
            else         stA(i + 1, nb);
            cpB(i + 1, nb);
            asm volatile("cp.async.commit_group;" ::: "memory");
            if (AM == 1 && i + 2 < NC) ldA(i + 2);
        }

        const uint32_t* As = &dyn[buf * CH_U32];
        const uint32_t* Bs = &dyn[(2 + buf) * CH_U32];
        #pragma unroll
        for (int ks = 0; ks < 4; ks++) {
            const int kk = ks * 8;
            uint32_t a[2][4];
            #pragma unroll
            for (int mt = 0; mt < 2; mt++) {
                int rbase = (wm + mt * 16 + grp) * BKP + kk;
                a[mt][0] = As[rbase + tig];
                a[mt][1] = As[rbase + 8 * BKP + tig];
                a[mt][2] = As[rbase + tig + 4];
                a[mt][3] = As[rbase + 8 * BKP + tig + 4];
            }
            #pragma unroll
            for (int nt = 0; nt < 8; nt++) {
                int nbase = (wn + nt * 8 + grp) * BKP + kk;
                uint32_t b0 = Bs[nbase + tig];
                uint32_t b1 = Bs[nbase + tig + 4];
                mma_m16n8k8(acc[0][nt], a[0], b0, b1);
                mma_m16n8k8(acc[1][nt], a[1], b0, b1);
            }
        }
        __syncthreads();
    }

    // ---- epilogue ----
    #pragma unroll
    for (int nt = 0; nt < 8; nt++) {
        float cs0 = 0.f, cq0 = 0.f, cs1 = 0.f, cq1 = 0.f;
        #pragma unroll
        for (int mt = 0; mt < 2; mt++) {
            #pragma unroll
            for (int half = 0; half < 2; half++) {
                int gm = row0 + wm + mt * 16 + grp + half * 8;
                if (gm >= M) continue;
                int col = col0 + wn + nt * 8 + 2 * tig;
                float v0 = acc[mt][nt][2 * half];
                float v1 = acc[mt][nt][2 * half + 1];
                if (EM == 0) {
                    cs0 += v0; cq0 += v0 * v0;
                    cs1 += v1; cq1 += v1 * v1;
                    *reinterpret_cast<float2*>(C + (size_t)gm * NCOLS + col) =
                        make_float2(v0, v1);
                } else {
                    v0 = fmaxf(v0 + __ldg(bias + col),     0.f);
                    v1 = fmaxf(v1 + __ldg(bias + col + 1), 0.f);
                    if (EM == 2) {
                        red_add_v2(pooled + (size_t)batch[gm] * NCOLS + col, v0, v1);
                    } else {
                        // h1 as bf16
                        reinterpret_cast<__nv_bfloat162*>(C)
                            [(size_t)gm * (NCOLS / 2) + (col >> 1)] =
                            __floats2bfloat162_rn(v0, v1);
                    }
                }
            }
        }
        if (EM == 0) {
            #pragma unroll
            for (int o = 4; o < 32; o <<= 1) {
                cs0 += __shfl_xor_sync(0xffffffffu, cs0, o);
                cq0 += __shfl_xor_sync(0xffffffffu, cq0, o);
                cs1 += __shfl_xor_sync(0xffffffffu, cs1, o);
                cq1 += __shfl_xor_sync(0xffffffffu, cq1, o);
            }
            if (grp == 0) {
                int lc = wn + nt * 8 + 2 * tig;
                atomicAdd(&s_sum[lc],     cs0);
                atomicAdd(&s_sq[lc],      cq0);
                atomicAdd(&s_sum[lc + 1], cs1);
                atomicAdd(&s_sq[lc + 1],  cq1);
            }
        }
    }
    if (EM == 0) {
        __syncthreads();
        if (tid < 128) {
            atomicAdd(&stats[col0 + tid],         s_sum[tid]);
            atomicAdd(&stats[NCOLS + col0 + tid], s_sq[tid]);
        }
    }
}

// ---------------------------------------------------------------------------
// Head MLP + end-of-run cleanup (re-zero cur/stats/pooled for next replay)
// ---------------------------------------------------------------------------
__global__ void head_kernel(float* __restrict__ pooled,
                            const float* __restrict__ Wl1,
                            const float* __restrict__ bl1,
                            const float* __restrict__ Wl2,
                            const float* __restrict__ bl2,
                            float* __restrict__ out, int OUTC, int N)
{
    __shared__ float sp[NCOLS];
    __shared__ float sh[NCOLS];
    int g = blockIdx.x, t = threadIdx.x;
    sp[t] = pooled[(size_t)g * NCOLS + t];
    pooled[(size_t)g * NCOLS + t] = 0.f;           // self-clean
    __syncthreads();
    float a = bl1[t];
    for (int k = 0; k < NCOLS; k++)
        a = fmaf(sp[k], Wl1[(size_t)k * NCOLS + t], a);
    sh[t] = fmaxf(a, 0.f);
    __syncthreads();
    if (t < 32 * OUTC) {
        int w = t >> 5, l = t & 31;
        float s = 0.f;
        for (int k = l; k < NCOLS; k += 32)
            s = fmaf(sh[k], Wl2[(size_t)k * OUTC + w], s);
        #pragma unroll
        for (int o = 16; o; o >>= 1)
            s += __shfl_down_sync(0xffffffffu, s, o);
        if (l == 0) out[(size_t)g * OUTC + w] = s + bl2[w];
    }
    // self-clean cur + stats for the next replay
    int id = g * blockDim.x + t;                   // 0..32767
    for (int i = id; i < N; i += NGRAPH * NCOLS) g_cur[i] = 0;
    if (id < 2 * NCOLS) g_stats[id] = 0.f;
}

// ---------------------------------------------------------------------------
// Launch.  Kernel order puts the first GEMM at launch index 5 (ncu -s 5).
// ---------------------------------------------------------------------------
extern "C" void kernel_launch(void* const* d_in, const int* in_sizes, int n_in,
                              void* d_out, int out_size)
{
    const float* x     = (const float*)d_in[0];
    const void*  ei    = d_in[1];
    const void*  batch = d_in[2];
    const float* W1a = (const float*)d_in[3];
    const float* g1  = (const float*)d_in[5];
    const float* be1 = (const float*)d_in[6];
    const float* W1b = (const float*)d_in[7];
    const float* b1b = (const float*)d_in[8];
    const float* W2a = (const float*)d_in[9];
    const float* g2  = (const float*)d_in[11];
    const float* be2 = (const float*)d_in[12];
    const float* W2b = (const float*)d_in[13];
    const float* b2b = (const float*)d_in[14];
    const float* Wl1 = (const float*)d_in[15];
    const float* bl1 = (const float*)d_in[16];
    const float* Wl2 = (const float*)d_in[17];
    const float* bl2 = (const float*)d_in[18];
    float* out = (float*)d_out;

    const int IN   = 128;
    const int N    = in_sizes[0] / IN;        // 50000
    const int E    = in_sizes[1] / 2;         // 800000
    const int OUTC = in_sizes[18];            // 10
    const int G    = out_size / OUTC;         // 64

    float *comb, *z, *stats, *pooled;
    __nv_bfloat16* h1b;
    float *Wt1a, *Wt1b, *Wt2a, *Wt2b;
    int *batchI, *offI, *curI, *bsumI;
    cudaGetSymbolAddress((void**)&comb,   g_agg);
    cudaGetSymbolAddress((void**)&z,      g_z);
    cudaGetSymbolAddress((void**)&h1b,    g_h1b);
    cudaGetSymbolAddress((void**)&stats,  g_stats);
    cudaGetSymbolAddress((void**)&pooled, g_pooled);
    cudaGetSymbolAddress((void**)&batchI, g_batch);
    cudaGetSymbolAddress((void**)&offI,   g_off);
    cudaGetSymbolAddress((void**)&curI,   g_cur);
    cudaGetSymbolAddress((void**)&bsumI,  g_bsum);
    cudaGetSymbolAddress((void**)&Wt1a,   g_Wt1a);
    cudaGetSymbolAddress((void**)&Wt1b,   g_Wt1b);
    cudaGetSymbolAddress((void**)&Wt2a,   g_Wt2a);
    cudaGetSymbolAddress((void**)&Wt2b,   g_Wt2b);

    cudaFuncSetAttribute(mma_gemm<0, 0>, cudaFuncAttributeMaxDynamicSharedMemorySize, GEMM_SMEM);
    cudaFuncSetAttribute(mma_gemm<1, 1>, cudaFuncAttributeMaxDynamicSharedMemorySize, GEMM_SMEM);
    cudaFuncSetAttribute(mma_gemm<1, 2>, cudaFuncAttributeMaxDynamicSharedMemorySize, GEMM_SMEM);

    const int eb = (E + 255) / 256;           // 3125
    const int nb = (N + 1023) / 1024;         // 49
    const int gatherBlocks = (N * 32 + 255) / 256;
    const int mtiles = (N + 127) / 128;
    const dim3 ggrid(4, mtiles);
    const float invN = 1.0f / (float)N;

    // 0: prep (convert+detect+hist | weight transposes)
    prep_kernel<<<dim3(eb, 5), 256>>>(ei, batch, E, N, W1a, W1b, W2a, W2b);
    // 1-3: CSR build
    scan_block<<<nb, 1024>>>(curI, offI, bsumI, N);
    scan_add2<<<nb, 1024>>>(offI, curI, bsumI, N, E);
    reorder_kernel<<<eb, 256>>>(E);
    // 4: layer-1 gather
    gather_csr<1><<<gatherBlocks, 256>>>(x, comb, N);
    // 5: layer-1 GEMM a  (profiled by ncu -s 5)
    mma_gemm<0, 0><<<ggrid, 256, GEMM_SMEM>>>(N, IN, comb, nullptr, nullptr, 0.f,
                                              Wt1a, nullptr, z, stats, nullptr, nullptr);
    // 6: layer-1 GEMM b (BN in-kernel, bf16 h1 out)
    mma_gemm<1, 1><<<ggrid, 256, GEMM_SMEM>>>(N, NCOLS, z, g1, be1, invN,
                                              Wt1b, b1b, (float*)h1b, stats, nullptr, nullptr);
    // 7: layer-2 gather (bf16 reads; zeroes stats)
    gather_bf16<<<gatherBlocks, 256>>>(h1b, comb, N);
    // 8: layer-2 GEMM a
    mma_gemm<0, 0><<<ggrid, 256, GEMM_SMEM>>>(N, NCOLS, comb, nullptr, nullptr, 0.f,
                                              Wt2a, nullptr, z, stats, nullptr, nullptr);
    // 9: layer-2 GEMM b (BN in-kernel, pooled RED)
    mma_gemm<1, 2><<<ggrid, 256, GEMM_SMEM>>>(N, NCOLS, z, g2, be2, invN,
                                              Wt2b, b2b, nullptr, stats, pooled, batchI);
    // 10: head + cleanup
    head_kernel<<<G, NCOLS>>>(pooled, Wl1, bl1, Wl2, bl2, out, OUTC, N);
}

// round 14
// speedup vs baseline: 1.1193x; 1.0135x over previous
#include <cuda_runtime.h>
#include <cuda_bf16.h>
#include <cstdint>
#include <cstddef>

// Problem constants (shapes fixed by the dataset)
#define NNODES 50000
#define NEDGES 800000
#define NCOLS  512
#define NGRAPH 64

// ---------------------------------------------------------------------------
// Scratch (device globals; zero-initialized at module load; no allocation)
// Self-cleaning: g_cur / g_stats / g_pooled re-zeroed by late kernels.
// ---------------------------------------------------------------------------
__device__ float         g_agg[(size_t)NNODES * NCOLS];   // comb (self+agg), tf32
__device__ __nv_bfloat16 g_zb[(size_t)NNODES * NCOLS];    // pre-BN z (bf16)
__device__ __nv_bfloat16 g_h1b[(size_t)NNODES * NCOLS];   // layer-1 output (bf16)
__device__ float         g_stats[2 * NCOLS];              // col sum / sumsq (fp32-exact)
__device__ float         g_pooled[(size_t)NGRAPH * NCOLS];
__device__ int           g_src[NEDGES];
__device__ int           g_dst[NEDGES];
__device__ int           g_batch[NNODES];
__device__ int           g_off[NNODES + 1];
__device__ int           g_cur[NNODES];
__device__ int           g_bsum[64];
__device__ int           g_ssrc[NEDGES];
__device__ float         g_Wt1a[(size_t)NCOLS * 128];     // [N][K] tf32 bits
__device__ float         g_Wt1b[(size_t)NCOLS * NCOLS];
__device__ float         g_Wt2a[(size_t)NCOLS * NCOLS];
__device__ float         g_Wt2b[(size_t)NCOLS * NCOLS];

// ---------------------------------------------------------------------------
// PTX helpers
// ---------------------------------------------------------------------------
__device__ __forceinline__ uint32_t smem_u32(const void* p) {
    uint32_t a;
    asm("{ .reg .u64 t; cvta.to.shared.u64 t, %1; cvt.u32.u64 %0, t; }"
        : "=r"(a) : "l"(p));
    return a;
}
__device__ __forceinline__ uint32_t f2tf32(float f) {
    uint32_t u;
    asm("cvt.rna.tf32.f32 %0, %1;" : "=r"(u) : "f"(f));
    return u;
}
__device__ __forceinline__ float4 round_tf32x4(float4 v) {
    return make_float4(__uint_as_float(f2tf32(v.x)), __uint_as_float(f2tf32(v.y)),
                       __uint_as_float(f2tf32(v.z)), __uint_as_float(f2tf32(v.w)));
}
__device__ __forceinline__ void cp16(uint32_t s, const void* g) {
    asm volatile("cp.async.cg.shared.global [%0], [%1], 16;"
                 :: "r"(s), "l"(g) : "memory");
}
__device__ __forceinline__ void red_add_v2(float* addr, float a, float b) {
    asm volatile("red.global.add.v2.f32 [%0], {%1, %2};"
                 :: "l"(addr), "f"(a), "f"(b) : "memory");
}
__device__ __forceinline__ void mma_m16n8k8(float* c, const uint32_t* a,
                                            uint32_t b0, uint32_t b1) {
    asm volatile("mma.sync.aligned.m16n8k8.row.col.f32.tf32.tf32.f32 "
                 "{%0,%1,%2,%3}, {%4,%5,%6,%7}, {%8,%9}, {%0,%1,%2,%3};"
                 : "+f"(c[0]), "+f"(c[1]), "+f"(c[2]), "+f"(c[3])
                 : "r"(a[0]), "r"(a[1]), "r"(a[2]), "r"(a[3]),
                   "r"(b0), "r"(b1));
}

// ---------------------------------------------------------------------------
// prep: (y==0) index detect + canonicalize + degree histogram
//       (y>=1) weight transpose + tf32 pre-round, one matrix per y
// ---------------------------------------------------------------------------
__global__ void prep_kernel(const void* __restrict__ ei,
                            const void* __restrict__ batch, int E, int N,
                            const float* __restrict__ W1a,
                            const float* __restrict__ W1b,
                            const float* __restrict__ W2a,
                            const float* __restrict__ W2b)
{
    if (blockIdx.y == 0) {
        int i = blockIdx.x * 256 + threadIdx.x;
        unsigned w = 0;
        if (i < E) w = ((const unsigned*)ei)[2 * i + 1];
        int is64 = (__syncthreads_or(w != 0u) == 0);
        if (i < E) {
            int s, d;
            if (is64) {
                s = (int)((const long long*)ei)[i];
                d = (int)((const long long*)ei)[E + i];
            } else {
                s = ((const int*)ei)[i];
                d = ((const int*)ei)[E + i];
            }
            g_src[i] = s;
            g_dst[i] = d;
            atomicAdd(&g_cur[d], 1);
        }
        if (i < N) {
            g_batch[i] = is64 ? (int)((const long long*)batch)[i]
                              : ((const int*)batch)[i];
        }
    } else {
        const float* W; float* T; int K;
        switch (blockIdx.y) {
            case 1:  W = W1a; T = g_Wt1a; K = 128;   break;
            case 2:  W = W1b; T = g_Wt1b; K = NCOLS; break;
            case 3:  W = W2a; T = g_Wt2a; K = NCOLS; break;
            default: W = W2b; T = g_Wt2b; K = NCOLS; break;
        }
        if ((int)blockIdx.x >= 16 * (K / 32)) return;
        __shared__ float t[32][33];
        int bx = (blockIdx.x & 15) * 32;      // n block
        int by = (blockIdx.x >> 4) * 32;      // k block
        int x = threadIdx.x & 31, y = threadIdx.x >> 5;   // y: 0..7
        #pragma unroll
        for (int i = 0; i < 32; i += 8)
            t[y + i][x] = W[(size_t)(by + y + i) * NCOLS + bx + x];
        __syncthreads();
        #pragma unroll
        for (int i = 0; i < 32; i += 8)
            T[(size_t)(bx + y + i) * K + by + x] =
                __uint_as_float(f2tf32(t[x][y + i]));
    }
}

// ---------------------------------------------------------------------------
// CSR build
// ---------------------------------------------------------------------------
__global__ void scan_block(const int* __restrict__ deg, int* __restrict__ off,
                           int* __restrict__ bsum, int n)
{
    __shared__ int wsum[32];
    __shared__ int woff[32];
    __shared__ int total;
    int tid = threadIdx.x, lane = tid & 31, wid = tid >> 5;
    int i = blockIdx.x * 1024 + tid;
    int v = (i < n) ? deg[i] : 0;
    int x = v;
    #pragma unroll
    for (int o = 1; o < 32; o <<= 1) {
        int y = __shfl_up_sync(0xffffffffu, x, o);
        if (lane >= o) x += y;
    }
    if (lane == 31) wsum[wid] = x;
    __syncthreads();
    if (tid < 32) {
        int w = wsum[tid];
        int s = w;
        #pragma unroll
        for (int o = 1; o < 32; o <<= 1) {
            int y = __shfl_up_sync(0xffffffffu, s, o);
            if (tid >= o) s += y;
        }
        woff[tid] = s - w;
        if (tid == 31) total = s;
    }
    __syncthreads();
    if (i < n) off[i] = x + woff[wid] - v;
    if (tid == 0) bsum[blockIdx.x] = total;
}

__global__ void scan_add2(int* __restrict__ off, int* __restrict__ cur,
                          const int* __restrict__ bsum, int n, int E)
{
    int b = blockIdx.x;
    int pre = 0;
    for (int j = 0; j < b; j++) pre += bsum[j];
    int i = b * 1024 + threadIdx.x;
    if (i < n) {
        int v = off[i] + pre;
        off[i] = v;
        cur[i] = v;
    }
    if (b == 0 && threadIdx.x == 0) off[n] = E;
}

// 4 edges per thread: overlap independent atomic RMW latencies
__global__ void reorder_kernel(int E)
{
    int i0 = (blockIdx.x * blockDim.x + threadIdx.x) * 4;
    #pragma unroll
    for (int j = 0; j < 4; j++) {
        int i = i0 + j;
        if (i < E) {
            int d = g_dst[i];
            int p = atomicAdd(&g_cur[d], 1);
            g_ssrc[p] = g_src[i];
        }
    }
}

// ---------------------------------------------------------------------------
// CSR gather (fp32 input, layer 1): out[v] = tf32(feat[v] + sum feat[u])
// ---------------------------------------------------------------------------
template<int R>
__global__ void gather_csr(const float* __restrict__ feat,
                           float* __restrict__ out, int Nn)
{
    int v = (blockIdx.x * blockDim.x + threadIdx.x) >> 5;
    int lane = threadIdx.x & 31;
    if (v >= Nn) return;
    int e0 = g_off[v], e1 = g_off[v + 1];
    const float4* fp = reinterpret_cast<const float4*>(feat);
    size_t selfb = (size_t)v * (R * 32);
    float4 acc[R];
    #pragma unroll
    for (int r = 0; r < R; r++) acc[r] = fp[selfb + lane + 32 * r];
    int e = e0;
    for (; e + 3 < e1; e += 4) {
        int s0 = g_ssrc[e], s1 = g_ssrc[e + 1], s2 = g_ssrc[e + 2], s3 = g_ssrc[e + 3];
        size_t b0 = (size_t)s0 * (R * 32), b1 = (size_t)s1 * (R * 32);
        size_t b2 = (size_t)s2 * (R * 32), b3 = (size_t)s3 * (R * 32);
        #pragma unroll
        for (int r = 0; r < R; r++) {
            float4 a = fp[b0 + lane + 32 * r];
            float4 b = fp[b1 + lane + 32 * r];
            float4 c = fp[b2 + lane + 32 * r];
            float4 d = fp[b3 + lane + 32 * r];
            acc[r].x += (a.x + b.x) + (c.x + d.x);
            acc[r].y += (a.y + b.y) + (c.y + d.y);
            acc[r].z += (a.z + b.z) + (c.z + d.z);
            acc[r].w += (a.w + b.w) + (c.w + d.w);
        }
    }
    for (; e < e1; e++) {
        size_t bA = (size_t)g_ssrc[e] * (R * 32);
        #pragma unroll
        for (int r = 0; r < R; r++) {
            float4 a = fp[bA + lane + 32 * r];
            acc[r].x += a.x; acc[r].y += a.y; acc[r].z += a.z; acc[r].w += a.w;
        }
    }
    float4* op = reinterpret_cast<float4*>(out);
    #pragma unroll
    for (int r = 0; r < R; r++) op[selfb + lane + 32 * r] = round_tf32x4(acc[r]);
}

// ---------------------------------------------------------------------------
// CSR gather (bf16 input, layer 2) + g_stats re-zero (block 0)
// ---------------------------------------------------------------------------
__device__ __forceinline__ void acc8_bf16(float* a, uint4 raw) {
    float2 p;
    p = __bfloat1622float2(*reinterpret_cast<__nv_bfloat162*>(&raw.x));
    a[0] += p.x; a[1] += p.y;
    p = __bfloat1622float2(*reinterpret_cast<__nv_bfloat162*>(&raw.y));
    a[2] += p.x; a[3] += p.y;
    p = __bfloat1622float2(*reinterpret_cast<__nv_bfloat162*>(&raw.z));
    a[4] += p.x; a[5] += p.y;
    p = __bfloat1622float2(*reinterpret_cast<__nv_bfloat162*>(&raw.w));
    a[6] += p.x; a[7] += p.y;
}

__global__ void gather_bf16(const __nv_bfloat16* __restrict__ feat,
                            float* __restrict__ out, int Nn)
{
    if (blockIdx.x == 0) {
        for (int c = threadIdx.x; c < 2 * NCOLS; c += 256) g_stats[c] = 0.f;
    }
    int v = (blockIdx.x * blockDim.x + threadIdx.x) >> 5;
    int lane = threadIdx.x & 31;
    if (v >= Nn) return;
    int e0 = g_off[v], e1 = g_off[v + 1];
    const uint4* fp = reinterpret_cast<const uint4*>(feat);   // 64 uint4/row
    size_t selfb = (size_t)v * 64;
    float acc[16];
    #pragma unroll
    for (int q = 0; q < 16; q++) acc[q] = 0.f;
    #pragma unroll
    for (int r = 0; r < 2; r++) acc8_bf16(&acc[8 * r], fp[selfb + lane + 32 * r]);
    int e = e0;
    for (; e + 3 < e1; e += 4) {
        size_t b0 = (size_t)g_ssrc[e]     * 64;
        size_t b1 = (size_t)g_ssrc[e + 1] * 64;
        size_t b2 = (size_t)g_ssrc[e + 2] * 64;
        size_t b3 = (size_t)g_ssrc[e + 3] * 64;
        #pragma unroll
        for (int r = 0; r < 2; r++) {
            uint4 ra = fp[b0 + lane + 32 * r];
            uint4 rb = fp[b1 + lane + 32 * r];
            uint4 rc = fp[b2 + lane + 32 * r];
            uint4 rd = fp[b3 + lane + 32 * r];
            acc8_bf16(&acc[8 * r], ra);
            acc8_bf16(&acc[8 * r], rb);
            acc8_bf16(&acc[8 * r], rc);
            acc8_bf16(&acc[8 * r], rd);
        }
    }
    for (; e < e1; e++) {
        size_t bA = (size_t)g_ssrc[e] * 64;
        #pragma unroll
        for (int r = 0; r < 2; r++) acc8_bf16(&acc[8 * r], fp[bA + lane + 32 * r]);
    }
    float4* op = reinterpret_cast<float4*>(out);
    #pragma unroll
    for (int r = 0; r < 2; r++) {
        int q = lane + 32 * r;
        float4 lo = round_tf32x4(make_float4(acc[8*r+0], acc[8*r+1], acc[8*r+2], acc[8*r+3]));
        float4 hi = round_tf32x4(make_float4(acc[8*r+4], acc[8*r+5], acc[8*r+6], acc[8*r+7]));
        op[(size_t)v * 128 + 2 * q]     = lo;
        op[(size_t)v * 128 + 2 * q + 1] = hi;
    }
}

// ---------------------------------------------------------------------------
// tf32 mma.sync GEMM, 2-stage cp.async, 1 sync per K-chunk.
//   AM==0 : A fp32 (tf32 pre-rounded) via cp.async
//   AM==1 : A bf16; A = relu(bf16(A)*scale+shift) staged via registers;
//           BN scale/shift computed in-kernel from stats (exact fp32 stats)
//   EM==0 : store acc as bf16 (z) + accumulate fp32 column stats
//   EM==1 : store relu(acc+bias) as bf16 (h1)
//   EM==2 : red-add relu(acc+bias) into pooled[batch[m]]
// ---------------------------------------------------------------------------
#define BKP 36
#define CH_U32 (128 * BKP)
#define GEMM_SMEM (4 * CH_U32 * 4)      // 73728 B (2-stage)

template<int AM, int EM>
__global__ void __launch_bounds__(256, 2)
mma_gemm(const int M, const int K,
         const void* __restrict__ A0v,
         const float* __restrict__ gamma, const float* __restrict__ beta,
         const float invN,
         const float* __restrict__ Bt, const float* __restrict__ bias,
         float* __restrict__ C, float* __restrict__ stats,
         float* __restrict__ pooled, const int* __restrict__ batch)
{
    extern __shared__ uint32_t dyn[];
    __shared__ float s_sum[128];
    __shared__ float s_sq[128];
    __shared__ float s_scale[NCOLS];
    __shared__ float s_shift[NCOLS];
    const uint32_t sbase = smem_u32(dyn);

    const int tid  = threadIdx.x;
    const int lane = tid & 31;
    const int warp = tid >> 5;
    const int grp  = lane >> 2;
    const int tig  = lane & 3;
    const int wm   = (warp >> 1) * 32;
    const int wn   = (warp & 1) * 64;
    const int col0 = blockIdx.x * 128;
    const int row0 = blockIdx.y * 128;

    const int slotRow = tid >> 3;        // B tile: 0..31
    const int slotC4  = tid & 7;
    const int aRow    = tid >> 2;        // A bf16 staging: 0..63 (and +64)
    const int aC8     = (tid & 3) * 8;   // bf16 offset within 32-chunk

    if (EM == 0 && tid < 128) { s_sum[tid] = 0.f; s_sq[tid] = 0.f; }
    if (AM == 1) {
        for (int c = tid; c < NCOLS; c += 256) {
            float mean = stats[c] * invN;
            float var  = stats[NCOLS + c] * invN - mean * mean;
            float s = gamma[c] * rsqrtf(var + 1e-5f);
            s_scale[c] = s;
            s_shift[c] = beta[c] - mean * s;
        }
    }

    float acc[2][8][4];
    #pragma unroll
    for (int mt = 0; mt < 2; mt++)
        #pragma unroll
        for (int nt = 0; nt < 8; nt++)
            #pragma unroll
            for (int q = 0; q < 4; q++) acc[mt][nt][q] = 0.f;

    const int NC = K >> 5;
    uint4 aR2[2];                        // AM==1: raw bf16 staging (2 rows x 8)

    auto cpB = [&](int ci, int buf) {
        const int k0 = ci << 5;
        #pragma unroll
        for (int r = 0; r < 4; r++) {
            int row = slotRow + r * 32;
            cp16(sbase + (2 + buf) * (CH_U32 * 4) +
                     (uint32_t)(row * BKP + slotC4 * 4) * 4,
                 Bt + (size_t)(col0 + row) * K + k0 + slotC4 * 4);
        }
    };
    auto cpA = [&](int ci, int buf) {    // AM==0: fp32 tf32-pre-rounded
        const float* A0 = (const float*)A0v;
        const int k0 = ci << 5;
        #pragma unroll
        for (int r = 0; r < 4; r++) {
            int row = slotRow + r * 32;
            int gr = row0 + row;
            if (gr < M) {
                cp16(sbase + buf * (CH_U32 * 4) +
                         (uint32_t)(row * BKP + slotC4 * 4) * 4,
                     A0 + (size_t)gr * K + k0 + slotC4 * 4);
            } else {
                *reinterpret_cast<uint4*>(&dyn[buf * CH_U32 + row * BKP + slotC4 * 4]) =
                    make_uint4(0u, 0u, 0u, 0u);
            }
        }
    };
    auto ldA = [&](int ci) {             // AM==1: bf16 input, 8 elems x 2 rows
        const __nv_bfloat16* Ab = (const __nv_bfloat16*)A0v;
        const int k0 = ci << 5;
        #pragma unroll
        for (int r = 0; r < 2; r++) {
            int gr = row0 + aRow + r * 64;
            aR2[r] = (gr < M)
                ? *reinterpret_cast<const uint4*>(Ab + (size_t)gr * K + k0 + aC8)
                : make_uint4(0u, 0u, 0u, 0u);
        }
    };
    auto stA = [&](int ci, int buf) {    // AM==1: bf16 -> BN+ReLU -> tf32 SMEM
        const int k0 = ci << 5;
        float4 sc0 = *reinterpret_cast<const float4*>(&s_scale[k0 + aC8]);
        float4 sc1 = *reinterpret_cast<const float4*>(&s_scale[k0 + aC8 + 4]);
        float4 sh0 = *reinterpret_cast<const float4*>(&s_shift[k0 + aC8]);
        float4 sh1 = *reinterpret_cast<const float4*>(&s_shift[k0 + aC8 + 4]);
        #pragma unroll
        for (int r = 0; r < 2; r++) {
            int row = aRow + r * 64;
            float v[8];
            float2 p;
            p = __bfloat1622float2(*reinterpret_cast<__nv_bfloat162*>(&aR2[r].x));
            v[0] = p.x; v[1] = p.y;
            p = __bfloat1622float2(*reinterpret_cast<__nv_bfloat162*>(&aR2[r].y));
            v[2] = p.x; v[3] = p.y;
            p = __bfloat1622float2(*reinterpret_cast<__nv_bfloat162*>(&aR2[r].z));
            v[4] = p.x; v[5] = p.y;
            p = __bfloat1622float2(*reinterpret_cast<__nv_bfloat162*>(&aR2[r].w));
            v[6] = p.x; v[7] = p.y;
            v[0] = fmaxf(fmaf(v[0], sc0.x, sh0.x), 0.f);
            v[1] = fmaxf(fmaf(v[1], sc0.y, sh0.y), 0.f);
            v[2] = fmaxf(fmaf(v[2], sc0.z, sh0.z), 0.f);
            v[3] = fmaxf(fmaf(v[3], sc0.w, sh0.w), 0.f);
            v[4] = fmaxf(fmaf(v[4], sc1.x, sh1.x), 0.f);
            v[5] = fmaxf(fmaf(v[5], sc1.y, sh1.y), 0.f);
            v[6] = fmaxf(fmaf(v[6], sc1.z, sh1.z), 0.f);
            v[7] = fmaxf(fmaf(v[7], sc1.w, sh1.w), 0.f);
            uint32_t* p0 = &dyn[buf * CH_U32 + row * BKP + aC8];
            *reinterpret_cast<uint4*>(p0) =
                make_uint4(f2tf32(v[0]), f2tf32(v[1]), f2tf32(v[2]), f2tf32(v[3]));
            *reinterpret_cast<uint4*>(p0 + 4) =
                make_uint4(f2tf32(v[4]), f2tf32(v[5]), f2tf32(v[6]), f2tf32(v[7]));
        }
    };

    // ---- prologue: chunk 0 ----
    if (AM == 0) cpA(0, 0);
    cpB(0, 0);
    asm volatile("cp.async.commit_group;" ::: "memory");
    if (AM == 1) {
        __syncthreads();          // s_scale/s_shift ready
        ldA(0);
        stA(0, 0);
        if (NC > 1) ldA(1);
    }

    // ---- mainloop ----
    for (int i = 0; i < NC; i++) {
        const int buf = i & 1;
        const int nb  = buf ^ 1;
        asm volatile("cp.async.wait_group 0;" ::: "memory");
        __syncthreads();
        if (i + 1 < NC) {
            if (AM == 0) cpA(i + 1, nb);
            else         stA(i + 1, nb);
            cpB(i + 1, nb);
            asm volatile("cp.async.commit_group;" ::: "memory");
            if (AM == 1 && i + 2 < NC) ldA(i + 2);
        }

        const uint32_t* As = &dyn[buf * CH_U32];
        const uint32_t* Bs = &dyn[(2 + buf) * CH_U32];
        #pragma unroll
        for (int ks = 0; ks < 4; ks++) {
            const int kk = ks * 8;
            uint32_t a[2][4];
            #pragma unroll
            for (int mt = 0; mt < 2; mt++) {
                int rbase = (wm + mt * 16 + grp) * BKP + kk;
                a[mt][0] = As[rbase + tig];
                a[mt][1] = As[rbase + 8 * BKP + tig];
                a[mt][2] = As[rbase + tig + 4];
                a[mt][3] = As[rbase + 8 * BKP + tig + 4];
            }
            #pragma unroll
            for (int nt = 0; nt < 8; nt++) {
                int nbase = (wn + nt * 8 + grp) * BKP + kk;
                uint32_t b0 = Bs[nbase + tig];
                uint32_t b1 = Bs[nbase + tig + 4];
                mma_m16n8k8(acc[0][nt], a[0], b0, b1);
                mma_m16n8k8(acc[1][nt], a[1], b0, b1);
            }
        }
        __syncthreads();
    }

    // ---- epilogue ----
    #pragma unroll
    for (int nt = 0; nt < 8; nt++) {
        float cs0 = 0.f, cq0 = 0.f, cs1 = 0.f, cq1 = 0.f;
        #pragma unroll
        for (int mt = 0; mt < 2; mt++) {
            #pragma unroll
            for (int half = 0; half < 2; half++) {
                int gm = row0 + wm + mt * 16 + grp + half * 8;
                if (gm >= M) continue;
                int col = col0 + wn + nt * 8 + 2 * tig;
                float v0 = acc[mt][nt][2 * half];
                float v1 = acc[mt][nt][2 * half + 1];
                if (EM == 0) {
                    cs0 += v0; cq0 += v0 * v0;
                    cs1 += v1; cq1 += v1 * v1;
                    // z as bf16 (stats already captured in fp32)
                    reinterpret_cast<__nv_bfloat162*>(C)
                        [(size_t)gm * (NCOLS / 2) + (col >> 1)] =
                        __floats2bfloat162_rn(v0, v1);
                } else {
                    v0 = fmaxf(v0 + __ldg(bias + col),     0.f);
                    v1 = fmaxf(v1 + __ldg(bias + col + 1), 0.f);
                    if (EM == 2) {
                        red_add_v2(pooled + (size_t)batch[gm] * NCOLS + col, v0, v1);
                    } else {
                        // h1 as bf16
                        reinterpret_cast<__nv_bfloat162*>(C)
                            [(size_t)gm * (NCOLS / 2) + (col >> 1)] =
                            __floats2bfloat162_rn(v0, v1);
                    }
                }
            }
        }
        if (EM == 0) {
            #pragma unroll
            for (int o = 4; o < 32; o <<= 1) {
                cs0 += __shfl_xor_sync(0xffffffffu, cs0, o);
                cq0 += __shfl_xor_sync(0xffffffffu, cq0, o);
                cs1 += __shfl_xor_sync(0xffffffffu, cs1, o);
                cq1 += __shfl_xor_sync(0xffffffffu, cq1, o);
            }
            if (grp == 0) {
                int lc = wn + nt * 8 + 2 * tig;
                atomicAdd(&s_sum[lc],     cs0);
                atomicAdd(&s_sq[lc],      cq0);
                atomicAdd(&s_sum[lc + 1], cs1);
                atomicAdd(&s_sq[lc + 1],  cq1);
            }
        }
    }
    if (EM == 0) {
        __syncthreads();
        if (tid < 128) {
            atomicAdd(&stats[col0 + tid],         s_sum[tid]);
            atomicAdd(&stats[NCOLS + col0 + tid], s_sq[tid]);
        }
    }
}

// ---------------------------------------------------------------------------
// Head MLP + end-of-run cleanup (re-zero cur/stats/pooled for next replay)
// ---------------------------------------------------------------------------
__global__ void head_kernel(float* __restrict__ pooled,
                            const float* __restrict__ Wl1,
                            const float* __restrict__ bl1,
                            const float* __restrict__ Wl2,
                            const float* __restrict__ bl2,
                            float* __restrict__ out, int OUTC, int N)
{
    __shared__ float sp[NCOLS];
    __shared__ float sh[NCOLS];
    int g = blockIdx.x, t = threadIdx.x;
    sp[t] = pooled[(size_t)g * NCOLS + t];
    pooled[(size_t)g * NCOLS + t] = 0.f;           // self-clean
    __syncthreads();
    float a = bl1[t];
    for (int k = 0; k < NCOLS; k++)
        a = fmaf(sp[k], Wl1[(size_t)k * NCOLS + t], a);
    sh[t] = fmaxf(a, 0.f);
    __syncthreads();
    if (t < 32 * OUTC) {
        int w = t >> 5, l = t & 31;
        float s = 0.f;
        for (int k = l; k < NCOLS; k += 32)
            s = fmaf(sh[k], Wl2[(size_t)k * OUTC + w], s);
        #pragma unroll
        for (int o = 16; o; o >>= 1)
            s += __shfl_down_sync(0xffffffffu, s, o);
        if (l == 0) out[(size_t)g * OUTC + w] = s + bl2[w];
    }
    // self-clean cur + stats for the next replay
    int id = g * blockDim.x + t;                   // 0..32767
    for (int i = id; i < N; i += NGRAPH * NCOLS) g_cur[i] = 0;
    if (id < 2 * NCOLS) g_stats[id] = 0.f;
}

// ---------------------------------------------------------------------------
// Launch
// ---------------------------------------------------------------------------
extern "C" void kernel_launch(void* const* d_in, const int* in_sizes, int n_in,
                              void* d_out, int out_size)
{
    const float* x     = (const float*)d_in[0];
    const void*  ei    = d_in[1];
    const void*  batch = d_in[2];
    const float* W1a = (const float*)d_in[3];
    const float* g1  = (const float*)d_in[5];
    const float* be1 = (const float*)d_in[6];
    const float* W1b = (const float*)d_in[7];
    const float* b1b = (const float*)d_in[8];
    const float* W2a = (const float*)d_in[9];
    const float* g2  = (const float*)d_in[11];
    const float* be2 = (const float*)d_in[12];
    const float* W2b = (const float*)d_in[13];
    const float* b2b = (const float*)d_in[14];
    const float* Wl1 = (const float*)d_in[15];
    const float* bl1 = (const float*)d_in[16];
    const float* Wl2 = (const float*)d_in[17];
    const float* bl2 = (const float*)d_in[18];
    float* out = (float*)d_out;

    const int IN   = 128;
    const int N    = in_sizes[0] / IN;        // 50000
    const int E    = in_sizes[1] / 2;         // 800000
    const int OUTC = in_sizes[18];            // 10
    const int G    = out_size / OUTC;         // 64

    float *comb, *stats, *pooled;
    __nv_bfloat16 *h1b, *zb;
    float *Wt1a, *Wt1b, *Wt2a, *Wt2b;
    int *batchI, *offI, *curI, *bsumI;
    cudaGetSymbolAddress((void**)&comb,   g_agg);
    cudaGetSymbolAddress((void**)&zb,     g_zb);
    cudaGetSymbolAddress((void**)&h1b,    g_h1b);
    cudaGetSymbolAddress((void**)&stats,  g_stats);
    cudaGetSymbolAddress((void**)&pooled, g_pooled);
    cudaGetSymbolAddress((void**)&batchI, g_batch);
    cudaGetSymbolAddress((void**)&offI,   g_off);
    cudaGetSymbolAddress((void**)&curI,   g_cur);
    cudaGetSymbolAddress((void**)&bsumI,  g_bsum);
    cudaGetSymbolAddress((void**)&Wt1a,   g_Wt1a);
    cudaGetSymbolAddress((void**)&Wt1b,   g_Wt1b);
    cudaGetSymbolAddress((void**)&Wt2a,   g_Wt2a);
    cudaGetSymbolAddress((void**)&Wt2b,   g_Wt2b);

    cudaFuncSetAttribute(mma_gemm<0, 0>, cudaFuncAttributeMaxDynamicSharedMemorySize, GEMM_SMEM);
    cudaFuncSetAttribute(mma_gemm<1, 1>, cudaFuncAttributeMaxDynamicSharedMemorySize, GEMM_SMEM);
    cudaFuncSetAttribute(mma_gemm<1, 2>, cudaFuncAttributeMaxDynamicSharedMemorySize, GEMM_SMEM);

    const int eb = (E + 255) / 256;           // 3125
    const int nb = (N + 1023) / 1024;         // 49
    const int gatherBlocks = (N * 32 + 255) / 256;
    const int mtiles = (N + 127) / 128;
    const dim3 ggrid(4, mtiles);
    const float invN = 1.0f / (float)N;

    // 0: prep (convert+detect+hist | weight transposes)
    prep_kernel<<<dim3(eb, 5), 256>>>(ei, batch, E, N, W1a, W1b, W2a, W2b);
    // 1-3: CSR build
    scan_block<<<nb, 1024>>>(curI, offI, bsumI, N);
    scan_add2<<<nb, 1024>>>(offI, curI, bsumI, N, E);
    reorder_kernel<<<(E + 1023) / 1024, 256>>>(E);
    // 4: layer-1 gather
    gather_csr<1><<<gatherBlocks, 256>>>(x, comb, N);
    // 5: layer-1 GEMM a (z out as bf16; fp32 stats)
    mma_gemm<0, 0><<<ggrid, 256, GEMM_SMEM>>>(N, IN, comb, nullptr, nullptr, 0.f,
                                              Wt1a, nullptr, (float*)zb, stats, nullptr, nullptr);
    // 6: layer-1 GEMM b (bf16 z in, BN in-kernel, bf16 h1 out)
    mma_gemm<1, 1><<<ggrid, 256, GEMM_SMEM>>>(N, NCOLS, zb, g1, be1, invN,
                                              Wt1b, b1b, (float*)h1b, stats, nullptr, nullptr);
    // 7: layer-2 gather (bf16 reads; zeroes stats)
    gather_bf16<<<gatherBlocks, 256>>>(h1b, comb, N);
    // 8: layer-2 GEMM a (z out as bf16)
    mma_gemm<0, 0><<<ggrid, 256, GEMM_SMEM>>>(N, NCOLS, comb, nullptr, nullptr, 0.f,
                                              Wt2a, nullptr, (float*)zb, stats, nullptr, nullptr);
    // 9: layer-2 GEMM b (bf16 z in, BN in-kernel, pooled RED)
    mma_gemm<1, 2><<<ggrid, 256, GEMM_SMEM>>>(N, NCOLS, zb, g2, be2, invN,
                                              Wt2b, b2b, nullptr, stats, pooled, batchI);
    // 10: head + cleanup
    head_kernel<<<G, NCOLS>>>(pooled, Wl1, bl1, Wl2, bl2, out, OUTC, N);
}

// round 17
// speedup vs baseline: 1.1928x; 1.0657x over previous
#include <cuda_runtime.h>
#include <cuda_bf16.h>
#include <cstdint>
#include <cstddef>

// Problem constants (shapes fixed by the dataset)
#define NNODES 50000
#define NEDGES 800000
#define NCOLS  512
#define NGRAPH 64

// ---------------------------------------------------------------------------
// Scratch (device globals; zero-initialized at module load; no allocation)
// Self-cleaning: g_cur / g_stats / g_pooled re-zeroed by late kernels.
// ---------------------------------------------------------------------------
__device__ float         g_agg[(size_t)NNODES * NCOLS];   // comb (self+agg), tf32
__device__ __nv_bfloat16 g_zb[(size_t)NNODES * NCOLS];    // pre-BN z (bf16)
__device__ __nv_bfloat16 g_h1b[(size_t)NNODES * NCOLS];   // layer-1 output (bf16)
__device__ float         g_stats[2 * NCOLS];              // col sum / sumsq (fp32)
__device__ float         g_pooled[(size_t)NGRAPH * NCOLS];
__device__ int           g_src[NEDGES];
__device__ int           g_dst[NEDGES];
__device__ int           g_batch[NNODES];
__device__ int           g_off[NNODES + 1];
__device__ int           g_cur[NNODES];
__device__ int           g_bsum[64];
__device__ int           g_ssrc[NEDGES];
__device__ float         g_Wt1a[(size_t)NCOLS * 128];     // [N][K] tf32 bits
__device__ float         g_Wt1b[(size_t)NCOLS * NCOLS];
__device__ float         g_Wt2a[(size_t)NCOLS * NCOLS];
__device__ float         g_Wt2b[(size_t)NCOLS * NCOLS];

// ---------------------------------------------------------------------------
// PTX helpers
// ---------------------------------------------------------------------------
__device__ __forceinline__ uint32_t smem_u32(const void* p) {
    uint32_t a;
    asm("{ .reg .u64 t; cvta.to.shared.u64 t, %1; cvt.u32.u64 %0, t; }"
        : "=r"(a) : "l"(p));
    return a;
}
__device__ __forceinline__ uint32_t f2tf32(float f) {
    uint32_t u;
    asm("cvt.rna.tf32.f32 %0, %1;" : "=r"(u) : "f"(f));
    return u;
}
__device__ __forceinline__ float4 round_tf32x4(float4 v) {
    return make_float4(__uint_as_float(f2tf32(v.x)), __uint_as_float(f2tf32(v.y)),
                       __uint_as_float(f2tf32(v.z)), __uint_as_float(f2tf32(v.w)));
}
__device__ __forceinline__ void cp16(uint32_t s, const void* g) {
    asm volatile("cp.async.cg.shared.global [%0], [%1], 16;"
                 :: "r"(s), "l"(g) : "memory");
}
__device__ __forceinline__ void red_add_v2(float* addr, float a, float b) {
    asm volatile("red.global.add.v2.f32 [%0], {%1, %2};"
                 :: "l"(addr), "f"(a), "f"(b) : "memory");
}
__device__ __forceinline__ void mma_m16n8k8(float* c, const uint32_t* a,
                                            uint32_t b0, uint32_t b1) {
    asm volatile("mma.sync.aligned.m16n8k8.row.col.f32.tf32.tf32.f32 "
                 "{%0,%1,%2,%3}, {%4,%5,%6,%7}, {%8,%9}, {%0,%1,%2,%3};"
                 : "+f"(c[0]), "+f"(c[1]), "+f"(c[2]), "+f"(c[3])
                 : "r"(a[0]), "r"(a[1]), "r"(a[2]), "r"(a[3]),
                   "r"(b0), "r"(b1));
}
// 4x (8x8 b16) tile load == one 16x8 tf32 A fragment / two 8x8 tf32 B frags
__device__ __forceinline__ void ldsm4(uint32_t* r, uint32_t addr) {
    asm volatile("ldmatrix.sync.aligned.m8n8.x4.shared.b16 {%0,%1,%2,%3}, [%4];"
                 : "=r"(r[0]), "=r"(r[1]), "=r"(r[2]), "=r"(r[3])
                 : "r"(addr));
}

// ---------------------------------------------------------------------------
// prep: (y==0) index detect + canonicalize + degree histogram
//       (y>=1) weight transpose + tf32 pre-round, one matrix per y
// ---------------------------------------------------------------------------
__global__ void prep_kernel(const void* __restrict__ ei,
                            const void* __restrict__ batch, int E, int N,
                            const float* __restrict__ W1a,
                            const float* __restrict__ W1b,
                            const float* __restrict__ W2a,
                            const float* __restrict__ W2b)
{
    if (blockIdx.y == 0) {
        int i = blockIdx.x * 256 + threadIdx.x;
        unsigned w = 0;
        if (i < E) w = ((const unsigned*)ei)[2 * i + 1];
        int is64 = (__syncthreads_or(w != 0u) == 0);
        if (i < E) {
            int s, d;
            if (is64) {
                s = (int)((const long long*)ei)[i];
                d = (int)((const long long*)ei)[E + i];
            } else {
                s = ((const int*)ei)[i];
                d = ((const int*)ei)[E + i];
            }
            g_src[i] = s;
            g_dst[i] = d;
            atomicAdd(&g_cur[d], 1);
        }
        if (i < N) {
            g_batch[i] = is64 ? (int)((const long long*)batch)[i]
                              : ((const int*)batch)[i];
        }
    } else {
        const float* W; float* T; int K;
        switch (blockIdx.y) {
            case 1:  W = W1a; T = g_Wt1a; K = 128;   break;
            case 2:  W = W1b; T = g_Wt1b; K = NCOLS; break;
            case 3:  W = W2a; T = g_Wt2a; K = NCOLS; break;
            default: W = W2b; T = g_Wt2b; K = NCOLS; break;
        }
        if ((int)blockIdx.x >= 16 * (K / 32)) return;
        __shared__ float t[32][33];
        int bx = (blockIdx.x & 15) * 32;      // n block
        int by = (blockIdx.x >> 4) * 32;      // k block
        int x = threadIdx.x & 31, y = threadIdx.x >> 5;   // y: 0..7
        #pragma unroll
        for (int i = 0; i < 32; i += 8)
            t[y + i][x] = W[(size_t)(by + y + i) * NCOLS + bx + x];
        __syncthreads();
        #pragma unroll
        for (int i = 0; i < 32; i += 8)
            T[(size_t)(bx + y + i) * K + by + x] =
                __uint_as_float(f2tf32(t[x][y + i]));
    }
}

// ---------------------------------------------------------------------------
// CSR build
// ---------------------------------------------------------------------------
__global__ void scan_block(const int* __restrict__ deg, int* __restrict__ off,
                           int* __restrict__ bsum, int n)
{
    __shared__ int wsum[32];
    __shared__ int woff[32];
    __shared__ int total;
    int tid = threadIdx.x, lane = tid & 31, wid = tid >> 5;
    int i = blockIdx.x * 1024 + tid;
    int v = (i < n) ? deg[i] : 0;
    int x = v;
    #pragma unroll
    for (int o = 1; o < 32; o <<= 1) {
        int y = __shfl_up_sync(0xffffffffu, x, o);
        if (lane >= o) x += y;
    }
    if (lane == 31) wsum[wid] = x;
    __syncthreads();
    if (tid < 32) {
        int w = wsum[tid];
        int s = w;
        #pragma unroll
        for (int o = 1; o < 32; o <<= 1) {
            int y = __shfl_up_sync(0xffffffffu, s, o);
            if (tid >= o) s += y;
        }
        woff[tid] = s - w;
        if (tid == 31) total = s;
    }
    __syncthreads();
    if (i < n) off[i] = x + woff[wid] - v;
    if (tid == 0) bsum[blockIdx.x] = total;
}

__global__ void scan_add2(int* __restrict__ off, int* __restrict__ cur,
                          const int* __restrict__ bsum, int n, int E)
{
    int b = blockIdx.x;
    int pre = 0;
    for (int j = 0; j < b; j++) pre += bsum[j];
    int i = b * 1024 + threadIdx.x;
    if (i < n) {
        int v = off[i] + pre;
        off[i] = v;
        cur[i] = v;
    }
    if (b == 0 && threadIdx.x == 0) off[n] = E;
}

__global__ void reorder_kernel(int E)
{
    int i = blockIdx.x * blockDim.x + threadIdx.x;
    if (i < E) {
        int d = g_dst[i];
        int p = atomicAdd(&g_cur[d], 1);
        g_ssrc[p] = g_src[i];
    }
}

// ---------------------------------------------------------------------------
// CSR gather (fp32 input, layer 1): out[v] = tf32(feat[v] + sum feat[u])
// ---------------------------------------------------------------------------
template<int R>
__global__ void gather_csr(const float* __restrict__ feat,
                           float* __restrict__ out, int Nn)
{
    int v = (blockIdx.x * blockDim.x + threadIdx.x) >> 5;
    int lane = threadIdx.x & 31;
    if (v >= Nn) return;
    int e0 = g_off[v], e1 = g_off[v + 1];
    const float4* fp = reinterpret_cast<const float4*>(feat);
    size_t selfb = (size_t)v * (R * 32);
    float4 acc[R];
    #pragma unroll
    for (int r = 0; r < R; r++) acc[r] = fp[selfb + lane + 32 * r];
    int e = e0;
    for (; e + 3 < e1; e += 4) {
        int s0 = g_ssrc[e], s1 = g_ssrc[e + 1], s2 = g_ssrc[e + 2], s3 = g_ssrc[e + 3];
        size_t b0 = (size_t)s0 * (R * 32), b1 = (size_t)s1 * (R * 32);
        size_t b2 = (size_t)s2 * (R * 32), b3 = (size_t)s3 * (R * 32);
        #pragma unroll
        for (int r = 0; r < R; r++) {
            float4 a = fp[b0 + lane + 32 * r];
            float4 b = fp[b1 + lane + 32 * r];
            float4 c = fp[b2 + lane + 32 * r];
            float4 d = fp[b3 + lane + 32 * r];
            acc[r].x += (a.x + b.x) + (c.x + d.x);
            acc[r].y += (a.y + b.y) + (c.y + d.y);
            acc[r].z += (a.z + b.z) + (c.z + d.z);
            acc[r].w += (a.w + b.w) + (c.w + d.w);
        }
    }
    for (; e < e1; e++) {
        size_t bA = (size_t)g_ssrc[e] * (R * 32);
        #pragma unroll
        for (int r = 0; r < R; r++) {
            float4 a = fp[bA + lane + 32 * r];
            acc[r].x += a.x; acc[r].y += a.y; acc[r].z += a.z; acc[r].w += a.w;
        }
    }
    float4* op = reinterpret_cast<float4*>(out);
    #pragma unroll
    for (int r = 0; r < R; r++) op[selfb + lane + 32 * r] = round_tf32x4(acc[r]);
}

// ---------------------------------------------------------------------------
// CSR gather (bf16 input, layer 2) + g_stats re-zero (block 0)
// ---------------------------------------------------------------------------
__device__ __forceinline__ void acc8_bf16(float* a, uint4 raw) {
    float2 p;
    p = __bfloat1622float2(*reinterpret_cast<__nv_bfloat162*>(&raw.x));
    a[0] += p.x; a[1] += p.y;
    p = __bfloat1622float2(*reinterpret_cast<__nv_bfloat162*>(&raw.y));
    a[2] += p.x; a[3] += p.y;
    p = __bfloat1622float2(*reinterpret_cast<__nv_bfloat162*>(&raw.z));
    a[4] += p.x; a[5] += p.y;
    p = __bfloat1622float2(*reinterpret_cast<__nv_bfloat162*>(&raw.w));
    a[6] += p.x; a[7] += p.y;
}

__global__ void gather_bf16(const __nv_bfloat16* __restrict__ feat,
                            float* __restrict__ out, int Nn)
{
    if (blockIdx.x == 0) {
        for (int c = threadIdx.x; c < 2 * NCOLS; c += 256) g_stats[c] = 0.f;
    }
    int v = (blockIdx.x * blockDim.x + threadIdx.x) >> 5;
    int lane = threadIdx.x & 31;
    if (v >= Nn) return;
    int e0 = g_off[v], e1 = g_off[v + 1];
    const uint4* fp = reinterpret_cast<const uint4*>(feat);   // 64 uint4/row
    size_t selfb = (size_t)v * 64;
    float acc[16];
    #pragma unroll
    for (int q = 0; q < 16; q++) acc[q] = 0.f;
    #pragma unroll
    for (int r = 0; r < 2; r++) acc8_bf16(&acc[8 * r], fp[selfb + lane + 32 * r]);
    int e = e0;
    for (; e + 3 < e1; e += 4) {
        size_t b0 = (size_t)g_ssrc[e]     * 64;
        size_t b1 = (size_t)g_ssrc[e + 1] * 64;
        size_t b2 = (size_t)g_ssrc[e + 2] * 64;
        size_t b3 = (size_t)g_ssrc[e + 3] * 64;
        #pragma unroll
        for (int r = 0; r < 2; r++) {
            uint4 ra = fp[b0 + lane + 32 * r];
            uint4 rb = fp[b1 + lane + 32 * r];
            uint4 rc = fp[b2 + lane + 32 * r];
            uint4 rd = fp[b3 + lane + 32 * r];
            acc8_bf16(&acc[8 * r], ra);
            acc8_bf16(&acc[8 * r], rb);
            acc8_bf16(&acc[8 * r], rc);
            acc8_bf16(&acc[8 * r], rd);
        }
    }
    for (; e < e1; e++) {
        size_t bA = (size_t)g_ssrc[e] * 64;
        #pragma unroll
        for (int r = 0; r < 2; r++) acc8_bf16(&acc[8 * r], fp[bA + lane + 32 * r]);
    }
    float4* op = reinterpret_cast<float4*>(out);
    #pragma unroll
    for (int r = 0; r < 2; r++) {
        int q = lane + 32 * r;
        float4 lo = round_tf32x4(make_float4(acc[8*r+0], acc[8*r+1], acc[8*r+2], acc[8*r+3]));
        float4 hi = round_tf32x4(make_float4(acc[8*r+4], acc[8*r+5], acc[8*r+6], acc[8*r+7]));
        op[(size_t)v * 128 + 2 * q]     = lo;
        op[(size_t)v * 128 + 2 * q + 1] = hi;
    }
}

// ---------------------------------------------------------------------------
// tf32 mma.sync GEMM, 2-stage cp.async, ldmatrix fragment loads.
//   AM==0 : A fp32 (tf32 pre-rounded) via cp.async
//   AM==1 : A bf16 (z); BN+ReLU via registers -> tf32 SMEM;
//           scale/shift computed in-kernel from fp32-exact stats
//   EM==0 : store acc as bf16 (z) + accumulate fp32 column stats
//   EM==1 : store relu(acc+bias) as bf16 (h1)
//   EM==2 : red-add relu(acc+bias) into pooled[batch[m]]
// ---------------------------------------------------------------------------
#define BKP 36
#define CH_U32 (128 * BKP)
#define GEMM_SMEM (4 * CH_U32 * 4)      // 73728 B (2-stage)

template<int AM, int EM>
__global__ void __launch_bounds__(256, 2)
mma_gemm(const int M, const int K,
         const void* __restrict__ A0v,
         const float* __restrict__ gamma, const float* __restrict__ beta,
         const float invN,
         const float* __restrict__ Bt, const float* __restrict__ bias,
         float* __restrict__ C, float* __restrict__ stats,
         float* __restrict__ pooled, const int* __restrict__ batch)
{
    extern __shared__ uint32_t dyn[];
    __shared__ float s_sum[128];
    __shared__ float s_sq[128];
    __shared__ float s_scale[NCOLS];
    __shared__ float s_shift[NCOLS];
    const uint32_t sbase = smem_u32(dyn);

    const int tid  = threadIdx.x;
    const int lane = tid & 31;
    const int warp = tid >> 5;
    const int grp  = lane >> 2;
    const int tig  = lane & 3;
    const int wm   = (warp >> 1) * 32;
    const int wn   = (warp & 1) * 64;
    const int col0 = blockIdx.x * 128;
    const int row0 = blockIdx.y * 128;

    const int slotRow = tid >> 3;        // B/A cp tile: 0..31
    const int slotC4  = tid & 7;
    const int aRow    = tid >> 2;        // AM==1 bf16 staging: 0..63 (+64)
    const int aC8     = (tid & 3) * 8;

    // ldmatrix per-thread byte offsets (row stride BKP u32 = BKP*4 bytes)
    // A fragment (16x8 tf32): rows wm+mt*16+(lane&15), u32 col +4 if lane>=16
    const uint32_t aOff0 = (uint32_t)((wm + (lane & 15)) * BKP + ((lane >> 4) << 2)) * 4;
    const uint32_t aOff1 = (uint32_t)((wm + 16 + (lane & 15)) * BKP + ((lane >> 4) << 2)) * 4;
    // B pair np (two 8x8 tf32 tiles): p=lane>>3; row += 8 if p>=2; col +4 u32 if p&1
    uint32_t bOff[4];
    {
        int p = lane >> 3;
        int rAdd = ((p & 2) ? 8 : 0) + (lane & 7);
        int cAdd = (p & 1) << 2;
        #pragma unroll
        for (int np = 0; np < 4; np++)
            bOff[np] = (uint32_t)((wn + np * 16 + rAdd) * BKP + cAdd) * 4;
    }

    if (EM == 0 && tid < 128) { s_sum[tid] = 0.f; s_sq[tid] = 0.f; }
    if (AM == 1) {
        for (int c = tid; c < NCOLS; c += 256) {
            float mean = stats[c] * invN;
            float var  = stats[NCOLS + c] * invN - mean * mean;
            float s = gamma[c] * rsqrtf(var + 1e-5f);
            s_scale[c] = s;
            s_shift[c] = beta[c] - mean * s;
        }
    }

    float acc[2][8][4];
    #pragma unroll
    for (int mt = 0; mt < 2; mt++)
        #pragma unroll
        for (int nt = 0; nt < 8; nt++)
            #pragma unroll
            for (int q = 0; q < 4; q++) acc[mt][nt][q] = 0.f;

    const int NC = K >> 5;
    uint4 aR2[2];                        // AM==1: raw bf16 staging

    auto cpB = [&](int ci, int buf) {
        const int k0 = ci << 5;
        #pragma unroll
        for (int r = 0; r < 4; r++) {
            int row = slotRow + r * 32;
            cp16(sbase + (2 + buf) * (CH_U32 * 4) +
                     (uint32_t)(row * BKP + slotC4 * 4) * 4,
                 Bt + (size_t)(col0 + row) * K + k0 + slotC4 * 4);
        }
    };
    auto cpA = [&](int ci, int buf) {    // AM==0: fp32 tf32-pre-rounded
        const float* A0 = (const float*)A0v;
        const int k0 = ci << 5;
        #pragma unroll
        for (int r = 0; r < 4; r++) {
            int row = slotRow + r * 32;
            int gr = row0 + row;
            if (gr < M) {
                cp16(sbase + buf * (CH_U32 * 4) +
                         (uint32_t)(row * BKP + slotC4 * 4) * 4,
                     A0 + (size_t)gr * K + k0 + slotC4 * 4);
            } else {
                *reinterpret_cast<uint4*>(&dyn[buf * CH_U32 + row * BKP + slotC4 * 4]) =
                    make_uint4(0u, 0u, 0u, 0u);
            }
        }
    };
    auto ldA = [&](int ci) {             // AM==1: bf16 input, 8 elems x 2 rows
        const __nv_bfloat16* Ab = (const __nv_bfloat16*)A0v;
        const int k0 = ci << 5;
        #pragma unroll
        for (int r = 0; r < 2; r++) {
            int gr = row0 + aRow + r * 64;
            aR2[r] = (gr < M)
                ? *reinterpret_cast<const uint4*>(Ab + (size_t)gr * K + k0 + aC8)
                : make_uint4(0u, 0u, 0u, 0u);
        }
    };
    auto stA = [&](int ci, int buf) {    // AM==1: bf16 -> BN+ReLU -> tf32 SMEM
        const int k0 = ci << 5;
        float4 sc0 = *reinterpret_cast<const float4*>(&s_scale[k0 + aC8]);
        float4 sc1 = *reinterpret_cast<const float4*>(&s_scale[k0 + aC8 + 4]);
        float4 sh0 = *reinterpret_cast<const float4*>(&s_shift[k0 + aC8]);
        float4 sh1 = *reinterpret_cast<const float4*>(&s_shift[k0 + aC8 + 4]);
        #pragma unroll
        for (int r = 0; r < 2; r++) {
            int row = aRow + r * 64;
            float v[8];
            float2 p;
            p = __bfloat1622float2(*reinterpret_cast<__nv_bfloat162*>(&aR2[r].x));
            v[0] = p.x; v[1] = p.y;
            p = __bfloat1622float2(*reinterpret_cast<__nv_bfloat162*>(&aR2[r].y));
            v[2] = p.x; v[3] = p.y;
            p = __bfloat1622float2(*reinterpret_cast<__nv_bfloat162*>(&aR2[r].z));
            v[4] = p.x; v[5] = p.y;
            p = __bfloat1622float2(*reinterpret_cast<__nv_bfloat162*>(&aR2[r].w));
            v[6] = p.x; v[7] = p.y;
            v[0] = fmaxf(fmaf(v[0], sc0.x, sh0.x), 0.f);
            v[1] = fmaxf(fmaf(v[1], sc0.y, sh0.y), 0.f);
            v[2] = fmaxf(fmaf(v[2], sc0.z, sh0.z), 0.f);
            v[3] = fmaxf(fmaf(v[3], sc0.w, sh0.w), 0.f);
            v[4] = fmaxf(fmaf(v[4], sc1.x, sh1.x), 0.f);
            v[5] = fmaxf(fmaf(v[5], sc1.y, sh1.y), 0.f);
            v[6] = fmaxf(fmaf(v[6], sc1.z, sh1.z), 0.f);
            v[7] = fmaxf(fmaf(v[7], sc1.w, sh1.w), 0.f);
            uint32_t* p0 = &dyn[buf * CH_U32 + row * BKP + aC8];
            *reinterpret_cast<uint4*>(p0) =
                make_uint4(f2tf32(v[0]), f2tf32(v[1]), f2tf32(v[2]), f2tf32(v[3]));
            *reinterpret_cast<uint4*>(p0 + 4) =
                make_uint4(f2tf32(v[4]), f2tf32(v[5]), f2tf32(v[6]), f2tf32(v[7]));
        }
    };

    // ---- prologue: chunk 0 ----
    if (AM == 0) cpA(0, 0);
    cpB(0, 0);
    asm volatile("cp.async.commit_group;" ::: "memory");
    if (AM == 1) {
        __syncthreads();          // s_scale/s_shift ready
        ldA(0);
        stA(0, 0);
        if (NC > 1) ldA(1);
    }

    // ---- mainloop ----
    for (int i = 0; i < NC; i++) {
        const int buf = i & 1;
        const int nb  = buf ^ 1;
        asm volatile("cp.async.wait_group 0;" ::: "memory");
        __syncthreads();
        if (i + 1 < NC) {
            if (AM == 0) cpA(i + 1, nb);
            else         stA(i + 1, nb);
            cpB(i + 1, nb);
            asm volatile("cp.async.commit_group;" ::: "memory");
            if (AM == 1 && i + 2 < NC) ldA(i + 2);
        }

        const uint32_t aBase = sbase + buf * (CH_U32 * 4);
        const uint32_t bBase = sbase + (2 + buf) * (CH_U32 * 4);
        #pragma unroll
        for (int ks = 0; ks < 4; ks++) {
            const uint32_t ko = (uint32_t)ks * 32;   // 8 u32 per step
            uint32_t a[2][4];
            ldsm4(a[0], aBase + aOff0 + ko);
            ldsm4(a[1], aBase + aOff1 + ko);
            #pragma unroll
            for (int h = 0; h < 2; h++) {
                uint32_t bb[2][4];
                ldsm4(bb[0], bBase + bOff[2 * h]     + ko);
                ldsm4(bb[1], bBase + bOff[2 * h + 1] + ko);
                #pragma unroll
                for (int q = 0; q < 4; q++) {        // nt = 4h+q
                    uint32_t b0 = bb[q >> 1][(q & 1) * 2];
                    uint32_t b1 = bb[q >> 1][(q & 1) * 2 + 1];
                    mma_m16n8k8(acc[0][4 * h + q], a[0], b0, b1);
                    mma_m16n8k8(acc[1][4 * h + q], a[1], b0, b1);
                }
            }
        }
        __syncthreads();
    }

    // ---- epilogue ----
    #pragma unroll
    for (int nt = 0; nt < 8; nt++) {
        float cs0 = 0.f, cq0 = 0.f, cs1 = 0.f, cq1 = 0.f;
        #pragma unroll
        for (int mt = 0; mt < 2; mt++) {
            #pragma unroll
            for (int half = 0; half < 2; half++) {
                int gm = row0 + wm + mt * 16 + grp + half * 8;
                if (gm >= M) continue;
                int col = col0 + wn + nt * 8 + 2 * tig;
                float v0 = acc[mt][nt][2 * half];
                float v1 = acc[mt][nt][2 * half + 1];
                if (EM == 0) {
                    cs0 += v0; cq0 += v0 * v0;
                    cs1 += v1; cq1 += v1 * v1;
                    reinterpret_cast<__nv_bfloat162*>(C)
                        [(size_t)gm * (NCOLS / 2) + (col >> 1)] =
                        __floats2bfloat162_rn(v0, v1);
                } else {
                    v0 = fmaxf(v0 + __ldg(bias + col),     0.f);
                    v1 = fmaxf(v1 + __ldg(bias + col + 1), 0.f);
                    if (EM == 2) {
                        red_add_v2(pooled + (size_t)batch[gm] * NCOLS + col, v0, v1);
                    } else {
                        reinterpret_cast<__nv_bfloat162*>(C)
                            [(size_t)gm * (NCOLS / 2) + (col >> 1)] =
                            __floats2bfloat162_rn(v0, v1);
                    }
                }
            }
        }
        if (EM == 0) {
            #pragma unroll
            for (int o = 4; o < 32; o <<= 1) {
                cs0 += __shfl_xor_sync(0xffffffffu, cs0, o);
                cq0 += __shfl_xor_sync(0xffffffffu, cq0, o);
                cs1 += __shfl_xor_sync(0xffffffffu, cs1, o);
                cq1 += __shfl_xor_sync(0xffffffffu, cq1, o);
            }
            if (grp == 0) {
                int lc = wn + nt * 8 + 2 * tig;
                atomicAdd(&s_sum[lc],     cs0);
                atomicAdd(&s_sq[lc],      cq0);
                atomicAdd(&s_sum[lc + 1], cs1);
                atomicAdd(&s_sq[lc + 1],  cq1);
            }
        }
    }
    if (EM == 0) {
        __syncthreads();
        if (tid < 128) {
            atomicAdd(&stats[col0 + tid],         s_sum[tid]);
            atomicAdd(&stats[NCOLS + col0 + tid], s_sq[tid]);
        }
    }
}

// ---------------------------------------------------------------------------
// Head MLP + end-of-run cleanup (re-zero cur/stats/pooled for next replay)
// ---------------------------------------------------------------------------
__global__ void head_kernel(float* __restrict__ pooled,
                            const float* __restrict__ Wl1,
                            const float* __restrict__ bl1,
                            const float* __restrict__ Wl2,
                            const float* __restrict__ bl2,
                            float* __restrict__ out, int OUTC, int N)
{
    __shared__ float sp[NCOLS];
    __shared__ float sh[NCOLS];
    int g = blockIdx.x, t = threadIdx.x;
    sp[t] = pooled[(size_t)g * NCOLS + t];
    pooled[(size_t)g * NCOLS + t] = 0.f;           // self-clean
    __syncthreads();
    float a = bl1[t];
    for (int k = 0; k < NCOLS; k++)
        a = fmaf(sp[k], Wl1[(size_t)k * NCOLS + t], a);
    sh[t] = fmaxf(a, 0.f);
    __syncthreads();
    if (t < 32 * OUTC) {
        int w = t >> 5, l = t & 31;
        float s = 0.f;
        for (int k = l; k < NCOLS; k += 32)
            s = fmaf(sh[k], Wl2[(size_t)k * OUTC + w], s);
        #pragma unroll
        for (int o = 16; o; o >>= 1)
            s += __shfl_down_sync(0xffffffffu, s, o);
        if (l == 0) out[(size_t)g * OUTC + w] = s + bl2[w];
    }
    // self-clean cur + stats for the next replay
    int id = g * blockDim.x + t;                   // 0..32767
    for (int i = id; i < N; i += NGRAPH * NCOLS) g_cur[i] = 0;
    if (id < 2 * NCOLS) g_stats[id] = 0.f;
}

// ---------------------------------------------------------------------------
// Launch
// ---------------------------------------------------------------------------
extern "C" void kernel_launch(void* const* d_in, const int* in_sizes, int n_in,
                              void* d_out, int out_size)
{
    const float* x     = (const float*)d_in[0];
    const void*  ei    = d_in[1];
    const void*  batch = d_in[2];
    const float* W1a = (const float*)d_in[3];
    const float* g1  = (const float*)d_in[5];
    const float* be1 = (const float*)d_in[6];
    const float* W1b = (const float*)d_in[7];
    const float* b1b = (const float*)d_in[8];
    const float* W2a = (const float*)d_in[9];
    const float* g2  = (const float*)d_in[11];
    const float* be2 = (const float*)d_in[12];
    const float* W2b = (const float*)d_in[13];
    const float* b2b = (const float*)d_in[14];
    const float* Wl1 = (const float*)d_in[15];
    const float* bl1 = (const float*)d_in[16];
    const float* Wl2 = (const float*)d_in[17];
    const float* bl2 = (const float*)d_in[18];
    float* out = (float*)d_out;

    const int IN   = 128;
    const int N    = in_sizes[0] / IN;        // 50000
    const int E    = in_sizes[1] / 2;         // 800000
    const int OUTC = in_sizes[18];            // 10
    const int G    = out_size / OUTC;         // 64

    float *comb, *stats, *pooled;
    __nv_bfloat16 *h1b, *zb;
    float *Wt1a, *Wt1b, *Wt2a, *Wt2b;
    int *batchI, *offI, *curI, *bsumI;
    cudaGetSymbolAddress((void**)&comb,   g_agg);
    cudaGetSymbolAddress((void**)&zb,     g_zb);
    cudaGetSymbolAddress((void**)&h1b,    g_h1b);
    cudaGetSymbolAddress((void**)&stats,  g_stats);
    cudaGetSymbolAddress((void**)&pooled, g_pooled);
    cudaGetSymbolAddress((void**)&batchI, g_batch);
    cudaGetSymbolAddress((void**)&offI,   g_off);
    cudaGetSymbolAddress((void**)&curI,   g_cur);
    cudaGetSymbolAddress((void**)&bsumI,  g_bsum);
    cudaGetSymbolAddress((void**)&Wt1a,   g_Wt1a);
    cudaGetSymbolAddress((void**)&Wt1b,   g_Wt1b);
    cudaGetSymbolAddress((void**)&Wt2a,   g_Wt2a);
    cudaGetSymbolAddress((void**)&Wt2b,   g_Wt2b);

    cudaFuncSetAttribute(mma_gemm<0, 0>, cudaFuncAttributeMaxDynamicSharedMemorySize, GEMM_SMEM);
    cudaFuncSetAttribute(mma_gemm<1, 1>, cudaFuncAttributeMaxDynamicSharedMemorySize, GEMM_SMEM);
    cudaFuncSetAttribute(mma_gemm<1, 2>, cudaFuncAttributeMaxDynamicSharedMemorySize, GEMM_SMEM);

    const int eb = (E + 255) / 256;           // 3125
    const int nb = (N + 1023) / 1024;         // 49
    const int gatherBlocks = (N * 32 + 255) / 256;
    const int mtiles = (N + 127) / 128;
    const dim3 ggrid(4, mtiles);
    const float invN = 1.0f / (float)N;

    // 0: prep (convert+detect+hist | weight transposes)
    prep_kernel<<<dim3(eb, 5), 256>>>(ei, batch, E, N, W1a, W1b, W2a, W2b);
    // 1-3: CSR build
    scan_block<<<nb, 1024>>>(curI, offI, bsumI, N);
    scan_add2<<<nb, 1024>>>(offI, curI, bsumI, N, E);
    reorder_kernel<<<eb, 256>>>(E);
    // 4: layer-1 gather
    gather_csr<1><<<gatherBlocks, 256>>>(x, comb, N);
    // 5: layer-1 GEMM a (z out as bf16; fp32 stats)
    mma_gemm<0, 0><<<ggrid, 256, GEMM_SMEM>>>(N, IN, comb, nullptr, nullptr, 0.f,
                                              Wt1a, nullptr, (float*)zb, stats, nullptr, nullptr);
    // 6: layer-1 GEMM b (bf16 z in, BN in-kernel, bf16 h1 out)
    mma_gemm<1, 1><<<ggrid, 256, GEMM_SMEM>>>(N, NCOLS, zb, g1, be1, invN,
                                              Wt1b, b1b, (float*)h1b, stats, nullptr, nullptr);
    // 7: layer-2 gather (bf16 reads; zeroes stats)
    gather_bf16<<<gatherBlocks, 256>>>(h1b, comb, N);
    // 8: layer-2 GEMM a (z out as bf16)
    mma_gemm<0, 0><<<ggrid, 256, GEMM_SMEM>>>(N, NCOLS, comb, nullptr, nullptr, 0.f,
                                              Wt2a, nullptr, (float*)zb, stats, nullptr, nullptr);
    // 9: layer-2 GEMM b (bf16 z in, BN in-kernel, pooled RED)
    mma_gemm<1, 2><<<ggrid, 256, GEMM_SMEM>>>(N, NCOLS, zb, g2, be2, invN,
                                              Wt2b, b2b, nullptr, stats, pooled, batchI);
    // 10: head + cleanup
    head_kernel<<<G, NCOLS>>>(pooled, Wl1, bl1, Wl2, bl2, out, OUTC, N);
}